// round 1
// baseline (speedup 1.0000x reference)
#include <cuda_runtime.h>
#include <cuda_bf16.h>

// Shapes (fixed for this problem)
#define B_  2
#define S_  2048
#define E_  2048
#define H_  16
#define D_  128
#define M_  (B_ * S_)     // 4096 rows for projections
#define HD  (H_ * D_)     // 2048

// ---------------------------------------------------------------------------
// Scratch (device globals: allocation-free per harness rules)
// ---------------------------------------------------------------------------
__device__ float g_q [M_ * HD];                         // 32 MB  [B,S,H,D]
__device__ float g_k [M_ * HD];                         // 32 MB
__device__ float g_v [M_ * HD];                         // 32 MB
__device__ float g_ao[M_ * HD];                         // 32 MB  attention out
__device__ float g_p [(size_t)B_ * H_ * S_ * S_];       // 512 MB scores/probs

// ---------------------------------------------------------------------------
// Generic 128x128x16 fp32 GEMM tile core.
//   BT=false : C[128,128] += A[128,K] * B[K,128]        (B row-major, ldb)
//   BT=true  : C[128,128] += A[128,K] * B[128,K]^T      (B row-major, ldb)
// Ab/Bb/Cb are already offset to this block's tile origin.
// All dims are multiples of tile sizes here, so no bounds checks.
// ---------------------------------------------------------------------------
template <bool BT>
__device__ __forceinline__ void gemm_core(const float* __restrict__ Ab,
                                          const float* __restrict__ Bb,
                                          float* __restrict__ Cb,
                                          int K, int lda, int ldb, int ldc)
{
    __shared__ float As[16][128];
    __shared__ float Bs[16][128];

    const int tid = threadIdx.x;           // 0..255
    const int ty  = tid >> 4;              // 0..15 : row group
    const int tx  = tid & 15;              // 0..15 : col group

    float acc[8][8];
#pragma unroll
    for (int i = 0; i < 8; i++)
#pragma unroll
        for (int j = 0; j < 8; j++) acc[i][j] = 0.0f;

    for (int kt = 0; kt < K; kt += 16) {
        // --- load A tile (128 rows x 16 k) transposed into As[k][row]
#pragma unroll
        for (int i = 0; i < 2; i++) {
            int v  = tid * 2 + i;          // 0..511 vec ids
            int r  = v >> 2;               // row 0..127
            int kk = (v & 3) << 2;         // k 0,4,8,12
            float4 a = *(const float4*)(Ab + (size_t)r * lda + kt + kk);
            As[kk + 0][r] = a.x; As[kk + 1][r] = a.y;
            As[kk + 2][r] = a.z; As[kk + 3][r] = a.w;
        }
        // --- load B tile
        if (BT) {
            // B is [N,K] row-major; tile = 128 n-rows x 16 k-cols, transpose
#pragma unroll
            for (int i = 0; i < 2; i++) {
                int v  = tid * 2 + i;
                int r  = v >> 2;
                int kk = (v & 3) << 2;
                float4 b = *(const float4*)(Bb + (size_t)r * ldb + kt + kk);
                Bs[kk + 0][r] = b.x; Bs[kk + 1][r] = b.y;
                Bs[kk + 2][r] = b.z; Bs[kk + 3][r] = b.w;
            }
        } else {
            // B is [K,N] row-major; tile = 16 k-rows x 128 n-cols, direct
#pragma unroll
            for (int i = 0; i < 2; i++) {
                int v = tid * 2 + i;
                int r = v >> 5;            // k-row 0..15
                int c = (v & 31) << 2;     // col 0..124
                *(float4*)&Bs[r][c] =
                    *(const float4*)(Bb + (size_t)(kt + r) * ldb + c);
            }
        }
        __syncthreads();

#pragma unroll
        for (int k = 0; k < 16; k++) {
            float a[8], b[8];
            *(float4*)(a)     = *(const float4*)&As[k][ty * 8];
            *(float4*)(a + 4) = *(const float4*)&As[k][ty * 8 + 4];
            *(float4*)(b)     = *(const float4*)&Bs[k][tx * 8];
            *(float4*)(b + 4) = *(const float4*)&Bs[k][tx * 8 + 4];
#pragma unroll
            for (int i = 0; i < 8; i++)
#pragma unroll
                for (int j = 0; j < 8; j++)
                    acc[i][j] = fmaf(a[i], b[j], acc[i][j]);
        }
        __syncthreads();
    }

#pragma unroll
    for (int i = 0; i < 8; i++) {
        float* cp = Cb + (size_t)(ty * 8 + i) * ldc + tx * 8;
        *(float4*)(cp)     = make_float4(acc[i][0], acc[i][1], acc[i][2], acc[i][3]);
        *(float4*)(cp + 4) = make_float4(acc[i][4], acc[i][5], acc[i][6], acc[i][7]);
    }
}

// ---------------------------------------------------------------------------
// 1) QKV projections: x[4096,2048] @ w[2048,2048] -> g_q/g_k/g_v
//    grid (16, 32, 3)
// ---------------------------------------------------------------------------
__global__ void __launch_bounds__(256) k_proj(const float* __restrict__ x,
                                              const float* __restrict__ wq,
                                              const float* __restrict__ wk,
                                              const float* __restrict__ wv)
{
    const float* w = (blockIdx.z == 0) ? wq : (blockIdx.z == 1) ? wk : wv;
    float*       o = (blockIdx.z == 0) ? g_q : (blockIdx.z == 1) ? g_k : g_v;
    gemm_core<false>(x + (size_t)blockIdx.y * 128 * E_,
                     w + blockIdx.x * 128,
                     o + (size_t)blockIdx.y * 128 * HD + blockIdx.x * 128,
                     E_, E_, HD, HD);
}

// ---------------------------------------------------------------------------
// 2) RMS norm over D=128 groups, in place on g_q (y=0) / g_k (y=1)
//    grid (8192, 2), block 256 (8 warps = 8 groups per block)
// ---------------------------------------------------------------------------
__global__ void __launch_bounds__(256) k_rmsnorm(const float* __restrict__ qs,
                                                 const float* __restrict__ ks)
{
    const int g    = blockIdx.x * 8 + (threadIdx.x >> 5);  // 0 .. 65535
    const int lane = threadIdx.x & 31;
    float*       t  = (blockIdx.y == 0) ? g_q : g_k;
    const float* sc = (blockIdx.y == 0) ? qs  : ks;

    float4* p = (float4*)(t + (size_t)g * 128) + lane;
    float4  v = *p;
    float ss = v.x * v.x + v.y * v.y + v.z * v.z + v.w * v.w;
#pragma unroll
    for (int o = 16; o; o >>= 1) ss += __shfl_xor_sync(0xffffffffu, ss, o);
    const float r = rsqrtf(ss * (1.0f / 128.0f) + 1e-6f);

    const float4 s = *((const float4*)sc + lane);
    v.x *= r * s.x; v.y *= r * s.y; v.z *= r * s.z; v.w *= r * s.w;
    *p = v;
}

// ---------------------------------------------------------------------------
// 3) scores[b,h] = qn[b,:,h,:] @ kn[b,:,h,:]^T   ([2048,128] x [128,2048])
//    grid (16, 16, 32)
// ---------------------------------------------------------------------------
__global__ void __launch_bounds__(256) k_scores()
{
    const int z = blockIdx.z, b = z >> 4, h = z & 15;
    const float* qb = g_q + (size_t)b * S_ * HD + h * D_;
    const float* kb = g_k + (size_t)b * S_ * HD + h * D_;
    float*       sb = g_p + (size_t)z * S_ * S_;
    gemm_core<true>(qb + (size_t)blockIdx.y * 128 * HD,
                    kb + (size_t)blockIdx.x * 128 * HD,
                    sb + (size_t)blockIdx.y * 128 * S_ + blockIdx.x * 128,
                    D_, HD, HD, S_);
}

// ---------------------------------------------------------------------------
// 4) row softmax over 2048-wide score rows, in place.  grid 65536, block 256
// ---------------------------------------------------------------------------
__global__ void __launch_bounds__(256) k_softmax()
{
    float* p = g_p + (size_t)blockIdx.x * S_;
    const int t    = threadIdx.x;
    const int lane = t & 31, warp = t >> 5;
    __shared__ float red[8];

    float4 v0 = *((float4*)p + t * 2);
    float4 v1 = *((float4*)p + t * 2 + 1);

    float m = fmaxf(fmaxf(fmaxf(v0.x, v0.y), fmaxf(v0.z, v0.w)),
                    fmaxf(fmaxf(v1.x, v1.y), fmaxf(v1.z, v1.w)));
#pragma unroll
    for (int o = 16; o; o >>= 1) m = fmaxf(m, __shfl_xor_sync(0xffffffffu, m, o));
    if (lane == 0) red[warp] = m;
    __syncthreads();
    m = red[0];
#pragma unroll
    for (int i = 1; i < 8; i++) m = fmaxf(m, red[i]);
    __syncthreads();  // all reads of red done before reuse

    v0.x = __expf(v0.x - m); v0.y = __expf(v0.y - m);
    v0.z = __expf(v0.z - m); v0.w = __expf(v0.w - m);
    v1.x = __expf(v1.x - m); v1.y = __expf(v1.y - m);
    v1.z = __expf(v1.z - m); v1.w = __expf(v1.w - m);

    float s = v0.x + v0.y + v0.z + v0.w + v1.x + v1.y + v1.z + v1.w;
#pragma unroll
    for (int o = 16; o; o >>= 1) s += __shfl_xor_sync(0xffffffffu, s, o);
    if (lane == 0) red[warp] = s;
    __syncthreads();
    s = red[0];
#pragma unroll
    for (int i = 1; i < 8; i++) s += red[i];

    const float inv = 1.0f / s;
    v0.x *= inv; v0.y *= inv; v0.z *= inv; v0.w *= inv;
    v1.x *= inv; v1.y *= inv; v1.z *= inv; v1.w *= inv;
    *((float4*)p + t * 2)     = v0;
    *((float4*)p + t * 2 + 1) = v1;
}

// ---------------------------------------------------------------------------
// 5) out[b,:,h,:] = probs[b,h] @ v[b,:,h,:]   ([2048,2048] x [2048,128])
//    grid (1, 16, 32)
// ---------------------------------------------------------------------------
__global__ void __launch_bounds__(256) k_av()
{
    const int z = blockIdx.z, b = z >> 4, h = z & 15;
    const float* A  = g_p  + (size_t)z * S_ * S_;
    const float* Bv = g_v  + (size_t)b * S_ * HD + h * D_;
    float*       C  = g_ao + (size_t)b * S_ * HD + h * D_;
    gemm_core<false>(A + (size_t)blockIdx.y * 128 * S_,
                     Bv,
                     C + (size_t)blockIdx.y * 128 * HD,
                     S_, S_, HD, HD);
}

// ---------------------------------------------------------------------------
// 6) output projection: g_ao[4096,2048] @ wo[2048,2048] -> out
//    grid (16, 32)
// ---------------------------------------------------------------------------
__global__ void __launch_bounds__(256) k_out(const float* __restrict__ wo,
                                             float* __restrict__ out)
{
    gemm_core<false>(g_ao + (size_t)blockIdx.y * 128 * HD,
                     wo + blockIdx.x * 128,
                     out + (size_t)blockIdx.y * 128 * E_ + blockIdx.x * 128,
                     HD, HD, E_, E_);
}

// ---------------------------------------------------------------------------
extern "C" void kernel_launch(void* const* d_in, const int* in_sizes, int n_in,
                              void* d_out, int out_size)
{
    const float* x  = (const float*)d_in[0];
    const float* wq = (const float*)d_in[1];
    const float* wk = (const float*)d_in[2];
    const float* wv = (const float*)d_in[3];
    const float* wo = (const float*)d_in[4];
    const float* qs = (const float*)d_in[5];
    const float* ks = (const float*)d_in[6];
    float* out = (float*)d_out;

    k_proj   <<<dim3(16, 32, 3), 256>>>(x, wq, wk, wv);
    k_rmsnorm<<<dim3(8192, 2),   256>>>(qs, ks);
    k_scores <<<dim3(16, 16, 32),256>>>();
    k_softmax<<<65536,           256>>>();
    k_av     <<<dim3(1, 16, 32), 256>>>();
    k_out    <<<dim3(16, 32),    256>>>(wo, out);
}

// round 2
// speedup vs baseline: 1.3144x; 1.3144x over previous
#include <cuda_runtime.h>
#include <cuda_bf16.h>
#include <cstdint>

// Shapes (fixed for this problem)
#define B_  2
#define S_  2048
#define E_  2048
#define H_  16
#define D_  128
#define M_  (B_ * S_)     // 4096 rows for projections
#define HD  (H_ * D_)     // 2048

// ---------------------------------------------------------------------------
// Scratch (device globals: allocation-free per harness rules)
// ---------------------------------------------------------------------------
__device__ float g_q [M_ * HD];                         // 32 MB  [B,S,H,D]
__device__ float g_k [M_ * HD];                         // 32 MB
__device__ float g_v [M_ * HD];                         // 32 MB
__device__ float g_ao[M_ * HD];                         // 32 MB  attention out
__device__ float g_p [(size_t)B_ * H_ * S_ * S_];       // 512 MB scores/probs

// ---------------------------------------------------------------------------
// tf32 helpers
// ---------------------------------------------------------------------------
__device__ __forceinline__ uint32_t f2tf32(float x) {
    uint32_t r;
    asm("cvt.rna.tf32.f32 %0, %1;" : "=r"(r) : "f"(x));
    return r;
}
__device__ __forceinline__ void split_tf32(float x, uint32_t& hi, uint32_t& lo) {
    hi = f2tf32(x);
    lo = f2tf32(x - __uint_as_float(hi));
}
__device__ __forceinline__ void mma_tf32(float* c, const uint32_t* a, const uint32_t* b) {
    asm volatile(
        "mma.sync.aligned.m16n8k8.row.col.f32.tf32.tf32.f32 "
        "{%0,%1,%2,%3},{%4,%5,%6,%7},{%8,%9},{%0,%1,%2,%3};"
        : "+f"(c[0]), "+f"(c[1]), "+f"(c[2]), "+f"(c[3])
        : "r"(a[0]), "r"(a[1]), "r"(a[2]), "r"(a[3]), "r"(b[0]), "r"(b[1]));
}

// swizzle permutation for k-major 16-word rows (conflict-free LDS & STS)
__device__ __forceinline__ int swzf(int m) { return (m & 3) ^ ((m >> 2) & 1); }

// ---------------------------------------------------------------------------
// 128x128 CTA tile, BK=16, 3xTF32 tensor-core GEMM.
//   BT=false : C = A[128,K] * B[K,128]      (B row-major, ldb)
//   BT=true  : C = A[128,K] * B[128,K]^T    (B row-major, ldb)
// 8 warps: warp (wm, wn) owns 64x32; each warp does 4x4 m16n8 tiles.
// ---------------------------------------------------------------------------
template <bool BT>
__device__ __forceinline__ void gemm_tf32(const float* __restrict__ Ab,
                                          const float* __restrict__ Bb,
                                          float* __restrict__ Cb,
                                          int K, int lda, int ldb, int ldc)
{
    // A tiles: 128 rows x 16 k, swizzled k-major rows of 16 words
    __shared__ uint32_t As_hi[128 * 16], As_lo[128 * 16];
    // B tiles: BT -> same layout as A (128 n-rows x 16 k); else [16][136] padded
    __shared__ uint32_t Bs_hi[BT ? 128 * 16 : 16 * 136];
    __shared__ uint32_t Bs_lo[BT ? 128 * 16 : 16 * 136];

    const int tid  = threadIdx.x;
    const int warp = tid >> 5;
    const int lane = tid & 31;
    const int g    = lane >> 2;       // group id (0..7)
    const int t    = lane & 3;        // thread-in-group (0..3)
    const int m0w  = (warp & 1) * 64; // warp M origin
    const int n0w  = (warp >> 1) * 32;// warp N origin

    float acc[4][4][4];
#pragma unroll
    for (int i = 0; i < 4; i++)
#pragma unroll
        for (int j = 0; j < 4; j++)
#pragma unroll
            for (int e = 0; e < 4; e++) acc[i][j][e] = 0.0f;

    for (int kt = 0; kt < K; kt += 16) {
        // ---- stage A tile (and B tile if BT) : rows x 16k, float4 along k
#pragma unroll
        for (int i = 0; i < 2; i++) {
            int v  = tid + i * 256;        // 0..511
            int r  = v >> 2;               // row 0..127
            int kv = v & 3;                // k-quad 0..3
            int idx = r * 16 + ((kv ^ swzf(r)) << 2);

            float4 a = *(const float4*)(Ab + (size_t)r * lda + kt + kv * 4);
            uint4 h, l;
            split_tf32(a.x, h.x, l.x); split_tf32(a.y, h.y, l.y);
            split_tf32(a.z, h.z, l.z); split_tf32(a.w, h.w, l.w);
            *(uint4*)&As_hi[idx] = h;
            *(uint4*)&As_lo[idx] = l;

            if (BT) {
                float4 b = *(const float4*)(Bb + (size_t)r * ldb + kt + kv * 4);
                split_tf32(b.x, h.x, l.x); split_tf32(b.y, h.y, l.y);
                split_tf32(b.z, h.z, l.z); split_tf32(b.w, h.w, l.w);
                *(uint4*)&Bs_hi[idx] = h;
                *(uint4*)&Bs_lo[idx] = l;
            }
        }
        if (!BT) {
            // B tile 16k x 128n, direct, padded rows of 136 words
#pragma unroll
            for (int i = 0; i < 2; i++) {
                int v  = tid + i * 256;
                int kr = v >> 5;            // 0..15
                int c4 = (v & 31) << 2;     // 0..124
                float4 b = *(const float4*)(Bb + (size_t)(kt + kr) * ldb + c4);
                uint4 h, l;
                split_tf32(b.x, h.x, l.x); split_tf32(b.y, h.y, l.y);
                split_tf32(b.z, h.z, l.z); split_tf32(b.w, h.w, l.w);
                int idx = kr * 136 + c4;
                *(uint4*)&Bs_hi[idx] = h;
                *(uint4*)&Bs_lo[idx] = l;
            }
        }
        __syncthreads();

#pragma unroll
        for (int ks = 0; ks < 2; ks++) {
            const int k0 = ks * 8;
            const int kq = k0 >> 2;

            // ---- B fragments for the 4 n-tiles
            uint32_t bh[4][2], bl[4][2];
#pragma unroll
            for (int nt = 0; nt < 4; nt++) {
                if (BT) {
                    int n  = n0w + nt * 8 + g;
                    int i0 = n * 16 + (((kq)     ^ swzf(n)) << 2) + t;
                    int i1 = n * 16 + (((kq + 1) ^ swzf(n)) << 2) + t;
                    bh[nt][0] = Bs_hi[i0]; bh[nt][1] = Bs_hi[i1];
                    bl[nt][0] = Bs_lo[i0]; bl[nt][1] = Bs_lo[i1];
                } else {
                    int n  = n0w + nt * 8 + g;
                    int i0 = (k0 + t)     * 136 + n;
                    int i1 = (k0 + t + 4) * 136 + n;
                    bh[nt][0] = Bs_hi[i0]; bh[nt][1] = Bs_hi[i1];
                    bl[nt][0] = Bs_lo[i0]; bl[nt][1] = Bs_lo[i1];
                }
            }

            // ---- loop m-tiles: load A frags, fire 3 mmas per (mt,nt)
#pragma unroll
            for (int mt = 0; mt < 4; mt++) {
                int ma = m0w + mt * 16 + g;
                int mb = ma + 8;
                int ia0 = ma * 16 + (((kq)     ^ swzf(ma)) << 2) + t;
                int ia1 = mb * 16 + (((kq)     ^ swzf(mb)) << 2) + t;
                int ia2 = ma * 16 + (((kq + 1) ^ swzf(ma)) << 2) + t;
                int ia3 = mb * 16 + (((kq + 1) ^ swzf(mb)) << 2) + t;
                uint32_t ah[4] = {As_hi[ia0], As_hi[ia1], As_hi[ia2], As_hi[ia3]};
                uint32_t al[4] = {As_lo[ia0], As_lo[ia1], As_lo[ia2], As_lo[ia3]};
#pragma unroll
                for (int nt = 0; nt < 4; nt++) {
                    mma_tf32(acc[mt][nt], ah, bh[nt]);   // hi*hi
                    mma_tf32(acc[mt][nt], ah, bl[nt]);   // hi*lo
                    mma_tf32(acc[mt][nt], al, bh[nt]);   // lo*hi
                }
            }
        }
        __syncthreads();
    }

    // ---- epilogue: each (mt,nt) tile -> two float2 stores per thread
#pragma unroll
    for (int mt = 0; mt < 4; mt++) {
#pragma unroll
        for (int nt = 0; nt < 4; nt++) {
            int r0 = m0w + mt * 16 + g;
            int c0 = n0w + nt * 8 + 2 * t;
            *(float2*)(Cb + (size_t)r0 * ldc + c0) =
                make_float2(acc[mt][nt][0], acc[mt][nt][1]);
            *(float2*)(Cb + (size_t)(r0 + 8) * ldc + c0) =
                make_float2(acc[mt][nt][2], acc[mt][nt][3]);
        }
    }
}

// ---------------------------------------------------------------------------
// 1) QKV projections: x[4096,2048] @ w[2048,2048] -> g_q/g_k/g_v
// ---------------------------------------------------------------------------
__global__ void __launch_bounds__(256) k_proj(const float* __restrict__ x,
                                              const float* __restrict__ wq,
                                              const float* __restrict__ wk,
                                              const float* __restrict__ wv)
{
    const float* w = (blockIdx.z == 0) ? wq : (blockIdx.z == 1) ? wk : wv;
    float*       o = (blockIdx.z == 0) ? g_q : (blockIdx.z == 1) ? g_k : g_v;
    gemm_tf32<false>(x + (size_t)blockIdx.y * 128 * E_,
                     w + blockIdx.x * 128,
                     o + (size_t)blockIdx.y * 128 * HD + blockIdx.x * 128,
                     E_, E_, HD, HD);
}

// ---------------------------------------------------------------------------
// 2) RMS norm over D=128 groups, in place on g_q / g_k
// ---------------------------------------------------------------------------
__global__ void __launch_bounds__(256) k_rmsnorm(const float* __restrict__ qs,
                                                 const float* __restrict__ ks)
{
    const int gg   = blockIdx.x * 8 + (threadIdx.x >> 5);
    const int lane = threadIdx.x & 31;
    float*       tp = (blockIdx.y == 0) ? g_q : g_k;
    const float* sc = (blockIdx.y == 0) ? qs  : ks;

    float4* p = (float4*)(tp + (size_t)gg * 128) + lane;
    float4  v = *p;
    float ss = v.x * v.x + v.y * v.y + v.z * v.z + v.w * v.w;
#pragma unroll
    for (int o = 16; o; o >>= 1) ss += __shfl_xor_sync(0xffffffffu, ss, o);
    const float r = rsqrtf(ss * (1.0f / 128.0f) + 1e-6f);

    const float4 s = *((const float4*)sc + lane);
    v.x *= r * s.x; v.y *= r * s.y; v.z *= r * s.z; v.w *= r * s.w;
    *p = v;
}

// ---------------------------------------------------------------------------
// 3) scores[b,h] = qn[b,:,h,:] @ kn[b,:,h,:]^T
// ---------------------------------------------------------------------------
__global__ void __launch_bounds__(256) k_scores()
{
    const int z = blockIdx.z, b = z >> 4, h = z & 15;
    const float* qb = g_q + (size_t)b * S_ * HD + h * D_;
    const float* kb = g_k + (size_t)b * S_ * HD + h * D_;
    float*       sb = g_p + (size_t)z * S_ * S_;
    gemm_tf32<true>(qb + (size_t)blockIdx.y * 128 * HD,
                    kb + (size_t)blockIdx.x * 128 * HD,
                    sb + (size_t)blockIdx.y * 128 * S_ + blockIdx.x * 128,
                    D_, HD, HD, S_);
}

// ---------------------------------------------------------------------------
// 4) row softmax over 2048-wide score rows, in place
// ---------------------------------------------------------------------------
__global__ void __launch_bounds__(256) k_softmax()
{
    float* p = g_p + (size_t)blockIdx.x * S_;
    const int t    = threadIdx.x;
    const int lane = t & 31, warp = t >> 5;
    __shared__ float red[8];

    float4 v0 = *((float4*)p + t * 2);
    float4 v1 = *((float4*)p + t * 2 + 1);

    float m = fmaxf(fmaxf(fmaxf(v0.x, v0.y), fmaxf(v0.z, v0.w)),
                    fmaxf(fmaxf(v1.x, v1.y), fmaxf(v1.z, v1.w)));
#pragma unroll
    for (int o = 16; o; o >>= 1) m = fmaxf(m, __shfl_xor_sync(0xffffffffu, m, o));
    if (lane == 0) red[warp] = m;
    __syncthreads();
    m = red[0];
#pragma unroll
    for (int i = 1; i < 8; i++) m = fmaxf(m, red[i]);
    __syncthreads();

    v0.x = __expf(v0.x - m); v0.y = __expf(v0.y - m);
    v0.z = __expf(v0.z - m); v0.w = __expf(v0.w - m);
    v1.x = __expf(v1.x - m); v1.y = __expf(v1.y - m);
    v1.z = __expf(v1.z - m); v1.w = __expf(v1.w - m);

    float s = v0.x + v0.y + v0.z + v0.w + v1.x + v1.y + v1.z + v1.w;
#pragma unroll
    for (int o = 16; o; o >>= 1) s += __shfl_xor_sync(0xffffffffu, s, o);
    if (lane == 0) red[warp] = s;
    __syncthreads();
    s = red[0];
#pragma unroll
    for (int i = 1; i < 8; i++) s += red[i];

    const float inv = 1.0f / s;
    v0.x *= inv; v0.y *= inv; v0.z *= inv; v0.w *= inv;
    v1.x *= inv; v1.y *= inv; v1.z *= inv; v1.w *= inv;
    *((float4*)p + t * 2)     = v0;
    *((float4*)p + t * 2 + 1) = v1;
}

// ---------------------------------------------------------------------------
// 5) out[b,:,h,:] = probs[b,h] @ v[b,:,h,:]
// ---------------------------------------------------------------------------
__global__ void __launch_bounds__(256) k_av()
{
    const int z = blockIdx.z, b = z >> 4, h = z & 15;
    const float* A  = g_p  + (size_t)z * S_ * S_;
    const float* Bv = g_v  + (size_t)b * S_ * HD + h * D_;
    float*       C  = g_ao + (size_t)b * S_ * HD + h * D_;
    gemm_tf32<false>(A + (size_t)blockIdx.y * 128 * S_,
                     Bv,
                     C + (size_t)blockIdx.y * 128 * HD,
                     S_, S_, HD, HD);
}

// ---------------------------------------------------------------------------
// 6) output projection: g_ao[4096,2048] @ wo[2048,2048] -> out
// ---------------------------------------------------------------------------
__global__ void __launch_bounds__(256) k_out(const float* __restrict__ wo,
                                             float* __restrict__ out)
{
    gemm_tf32<false>(g_ao + (size_t)blockIdx.y * 128 * HD,
                     wo + blockIdx.x * 128,
                     out + (size_t)blockIdx.y * 128 * E_ + blockIdx.x * 128,
                     HD, HD, E_, E_);
}

// ---------------------------------------------------------------------------
extern "C" void kernel_launch(void* const* d_in, const int* in_sizes, int n_in,
                              void* d_out, int out_size)
{
    const float* x  = (const float*)d_in[0];
    const float* wq = (const float*)d_in[1];
    const float* wk = (const float*)d_in[2];
    const float* wv = (const float*)d_in[3];
    const float* wo = (const float*)d_in[4];
    const float* qs = (const float*)d_in[5];
    const float* ks = (const float*)d_in[6];
    float* out = (float*)d_out;

    k_proj   <<<dim3(16, 32, 3), 256>>>(x, wq, wk, wv);
    k_rmsnorm<<<dim3(8192, 2),   256>>>(qs, ks);
    k_scores <<<dim3(16, 16, 32),256>>>();
    k_softmax<<<65536,           256>>>();
    k_av     <<<dim3(1, 16, 32), 256>>>();
    k_out    <<<dim3(16, 32),    256>>>(wo, out);
}

// round 4
// speedup vs baseline: 2.8508x; 2.1690x over previous
#include <cuda_runtime.h>
#include <cuda_bf16.h>
#include <cstdint>

#define B_  2
#define S_  2048
#define E_  2048
#define H_  16
#define D_  128
#define M_  (B_ * S_)     // 4096
#define HD  2048

// ---------------------------------------------------------------------------
// Scratch (device globals — allocation-free per harness rules)
// ---------------------------------------------------------------------------
__device__ float g_q [(size_t)M_ * HD];                    // fp32 [B,S,H,D]
__device__ float g_k [(size_t)M_ * HD];
__device__ float g_v [(size_t)M_ * HD];
__device__ float g_ao[(size_t)M_ * HD];
__device__ float g_p [(size_t)B_ * H_ * S_ * S_];          // fp32 scores

// bf16 hi/lo split operands (all k-major rows, stride 2048)
__device__ __nv_bfloat16 g_xh [(size_t)M_ * E_],  g_xl [(size_t)M_ * E_];
__device__ __nv_bfloat16 g_wqh[(size_t)HD * E_],  g_wql[(size_t)HD * E_];   // [n][k]
__device__ __nv_bfloat16 g_wkh[(size_t)HD * E_],  g_wkl[(size_t)HD * E_];
__device__ __nv_bfloat16 g_wvh[(size_t)HD * E_],  g_wvl[(size_t)HD * E_];
__device__ __nv_bfloat16 g_woh[(size_t)E_ * HD],  g_wol[(size_t)E_ * HD];   // [n][k]
__device__ __nv_bfloat16 g_qnh[(size_t)M_ * HD],  g_qnl[(size_t)M_ * HD];
__device__ __nv_bfloat16 g_knh[(size_t)M_ * HD],  g_knl[(size_t)M_ * HD];
__device__ __nv_bfloat16 g_vth[(size_t)B_*H_*D_*S_], g_vtl[(size_t)B_*H_*D_*S_]; // [z][d][s]
__device__ __nv_bfloat16 g_ph [(size_t)B_*H_*S_*S_], g_pl [(size_t)B_*H_*S_*S_];
__device__ __nv_bfloat16 g_aoh[(size_t)M_ * HD],  g_aol[(size_t)M_ * HD];

// ---------------------------------------------------------------------------
// helpers
// ---------------------------------------------------------------------------
__device__ __forceinline__ void cpa16(uint32_t dst, const void* src) {
    asm volatile("cp.async.cg.shared.global [%0], [%1], 16;\n" :: "r"(dst), "l"(src));
}
#define CP_COMMIT() asm volatile("cp.async.commit_group;\n" ::: "memory")
template <int N>
__device__ __forceinline__ void cp_wait() {
    asm volatile("cp.async.wait_group %0;\n" :: "n"(N) : "memory");
}
#define LDMX4(r, a) \
    asm volatile("ldmatrix.sync.aligned.m8n8.x4.shared.b16 {%0,%1,%2,%3}, [%4];" \
        : "=r"((r)[0]), "=r"((r)[1]), "=r"((r)[2]), "=r"((r)[3]) : "r"(a))
#define LDMX2(r, a) \
    asm volatile("ldmatrix.sync.aligned.m8n8.x2.shared.b16 {%0,%1}, [%2];" \
        : "=r"((r)[0]), "=r"((r)[1]) : "r"(a))

__device__ __forceinline__ void mma_bf16(float* c, const uint32_t* a, const uint32_t* b) {
    asm volatile(
        "mma.sync.aligned.m16n8k16.row.col.f32.bf16.bf16.f32 "
        "{%0,%1,%2,%3},{%4,%5,%6,%7},{%8,%9},{%0,%1,%2,%3};"
        : "+f"(c[0]), "+f"(c[1]), "+f"(c[2]), "+f"(c[3])
        : "r"(a[0]), "r"(a[1]), "r"(a[2]), "r"(a[3]), "r"(b[0]), "r"(b[1]));
}

__device__ __forceinline__ void split_bf16(float x, __nv_bfloat16& h, __nv_bfloat16& l) {
    h = __float2bfloat16_rn(x);
    l = __float2bfloat16_rn(x - __bfloat162float(h));
}

// ---------------------------------------------------------------------------
// 128x128 CTA tile bf16 3-term GEMM, BK=64, 2-stage cp.async pipeline.
// C[128,128] = (Ah+Al)[128,K] * (Bh+Bl)[128,K]^T, all strides 2048 elems.
// SMEM per stage: 4 arrays x (128 rows x 128B swizzled) = 64KB. 2 stages.
// ---------------------------------------------------------------------------
__device__ __forceinline__ void gemm_bf3(const __nv_bfloat16* __restrict__ Ah,
                                         const __nv_bfloat16* __restrict__ Al,
                                         const __nv_bfloat16* __restrict__ Bh,
                                         const __nv_bfloat16* __restrict__ Bl,
                                         float* __restrict__ C, int K)
{
    extern __shared__ char dsm[];
    const uint32_t s0 = ((uint32_t)__cvta_generic_to_shared(dsm) + 1023) & ~1023u;

    const int tid  = threadIdx.x;
    const int warp = tid >> 5;
    const int lane = tid & 31;
    const int g    = lane >> 2;
    const int t    = lane & 3;
    const int m0w  = (warp & 1) * 64;
    const int n0w  = (warp >> 1) * 32;

    const __nv_bfloat16* srcs[4] = {Ah, Al, Bh, Bl};

    float acc[4][4][4];
#pragma unroll
    for (int i = 0; i < 4; i++)
#pragma unroll
        for (int j = 0; j < 4; j++)
#pragma unroll
            for (int e = 0; e < 4; e++) acc[i][j][e] = 0.0f;

    const int nch = K >> 6;

    // ---- issue one stage's cp.asyncs (chunk c into buffer c&1)
    auto issue = [&](int c) {
        const uint32_t stb = s0 + (uint32_t)(c & 1) * 65536u;
        const int kt = c * 64;
#pragma unroll
        for (int arr = 0; arr < 4; arr++) {
            const __nv_bfloat16* sp = srcs[arr];
            const uint32_t ab = stb + (uint32_t)arr * 16384u;
#pragma unroll
            for (int j = 0; j < 4; j++) {
                const int loc = tid + j * 256;        // 0..1023
                const int row = loc >> 3;
                const int ch  = loc & 7;
                const uint32_t off = (uint32_t)row * 128u
                                   + (uint32_t)((ch ^ (row & 7)) << 4);
                cpa16(ab + off, sp + (size_t)row * 2048 + kt + ch * 8);
            }
        }
        CP_COMMIT();
    };

    issue(0);

    for (int c = 0; c < nch; c++) {
        if (c + 1 < nch) { issue(c + 1); cp_wait<1>(); }
        else             { cp_wait<0>(); }
        __syncthreads();

        const uint32_t stb = s0 + (uint32_t)(c & 1) * 65536u;
        const uint32_t aB  = stb;              // Ah; Al at +16384
        const uint32_t bB  = stb + 32768u;     // Bh; Bl at +16384

#pragma unroll
        for (int ks = 0; ks < 4; ks++) {
            // B fragments (hi & lo) for the 4 n-tiles
            uint32_t bh[4][2], bl[4][2];
#pragma unroll
            for (int nt = 0; nt < 4; nt++) {
                const int rb = n0w + nt * 8 + (lane & 7);
                const int cb = ks * 2 + ((lane >> 3) & 1);
                const uint32_t off = (uint32_t)rb * 128u
                                   + (uint32_t)((cb ^ (rb & 7)) << 4);
                LDMX2(bh[nt], bB + off);
                LDMX2(bl[nt], bB + 16384u + off);
            }
            // A fragments + 3-term MMAs
#pragma unroll
            for (int mt = 0; mt < 4; mt++) {
                const int ra = m0w + mt * 16 + (lane & 15);
                const int ca = ks * 2 + (lane >> 4);
                const uint32_t off = (uint32_t)ra * 128u
                                   + (uint32_t)((ca ^ (ra & 7)) << 4);
                uint32_t ah[4], al[4];
                LDMX4(ah, aB + off);
                LDMX4(al, aB + 16384u + off);
#pragma unroll
                for (int nt = 0; nt < 4; nt++) {
                    mma_bf16(acc[mt][nt], ah, bh[nt]);   // hi*hi
                    mma_bf16(acc[mt][nt], ah, bl[nt]);   // hi*lo
                    mma_bf16(acc[mt][nt], al, bh[nt]);   // lo*hi
                }
            }
        }
        __syncthreads();
    }

    // ---- epilogue
#pragma unroll
    for (int mt = 0; mt < 4; mt++) {
#pragma unroll
        for (int nt = 0; nt < 4; nt++) {
            const int r0 = m0w + mt * 16 + g;
            const int c0 = n0w + nt * 8 + 2 * t;
            *(float2*)(C + (size_t)r0 * 2048 + c0) =
                make_float2(acc[mt][nt][0], acc[mt][nt][1]);
            *(float2*)(C + (size_t)(r0 + 8) * 2048 + c0) =
                make_float2(acc[mt][nt][2], acc[mt][nt][3]);
        }
    }
}

// ---------------------------------------------------------------------------
// GEMM wrapper kernels (all 128x128 tiles)
// ---------------------------------------------------------------------------
__global__ void __launch_bounds__(256, 1) kg_proj()
{
    const int z = blockIdx.z;
    const __nv_bfloat16* wh = (z == 0) ? g_wqh : (z == 1) ? g_wkh : g_wvh;
    const __nv_bfloat16* wl = (z == 0) ? g_wql : (z == 1) ? g_wkl : g_wvl;
    float* o = (z == 0) ? g_q : (z == 1) ? g_k : g_v;
    const size_t ao = (size_t)blockIdx.y * 128 * 2048;
    const size_t bo = (size_t)blockIdx.x * 128 * 2048;
    gemm_bf3(g_xh + ao, g_xl + ao, wh + bo, wl + bo,
             o + ao + blockIdx.x * 128, E_);
}

__global__ void __launch_bounds__(256, 1) kg_scores()
{
    const int z = blockIdx.z, b = z >> 4, h = z & 15;
    const size_t ao = ((size_t)b * S_ + blockIdx.y * 128) * 2048 + h * 128;
    const size_t bo = ((size_t)b * S_ + blockIdx.x * 128) * 2048 + h * 128;
    float* C = g_p + (size_t)z * S_ * S_ + (size_t)blockIdx.y * 128 * S_
                   + blockIdx.x * 128;
    gemm_bf3(g_qnh + ao, g_qnl + ao, g_knh + bo, g_knl + bo, C, D_);
}

__global__ void __launch_bounds__(256, 1) kg_av()
{
    const int z = blockIdx.y, b = z >> 4, h = z & 15;
    const size_t ao = (size_t)z * S_ * S_ + (size_t)blockIdx.x * 128 * 2048;
    const size_t bo = (size_t)z * D_ * S_;
    float* C = g_ao + ((size_t)b * S_ + blockIdx.x * 128) * 2048 + h * 128;
    gemm_bf3(g_ph + ao, g_pl + ao, g_vth + bo, g_vtl + bo, C, S_);
}

__global__ void __launch_bounds__(256, 1) kg_out(float* out)
{
    const size_t ao = (size_t)blockIdx.y * 128 * 2048;
    const size_t bo = (size_t)blockIdx.x * 128 * 2048;
    gemm_bf3(g_aoh + ao, g_aol + ao, g_woh + bo, g_wol + bo,
             out + ao + blockIdx.x * 128, HD);
}

// ---------------------------------------------------------------------------
// Prep / conversion kernels
// ---------------------------------------------------------------------------
__global__ void k_prep_w(const float* __restrict__ wq, const float* __restrict__ wk,
                         const float* __restrict__ wv, const float* __restrict__ wo)
{
    __shared__ float tbuf[32][33];
    const int z = blockIdx.z;
    const float* src = (z == 0) ? wq : (z == 1) ? wk : (z == 2) ? wv : wo;
    __nv_bfloat16* dh = (z == 0) ? g_wqh : (z == 1) ? g_wkh : (z == 2) ? g_wvh : g_woh;
    __nv_bfloat16* dl = (z == 0) ? g_wql : (z == 1) ? g_wkl : (z == 2) ? g_wvl : g_wol;
    const int x0 = blockIdx.x * 32, y0 = blockIdx.y * 32;
    const int tx = threadIdx.x, ty = threadIdx.y;
#pragma unroll
    for (int j = ty; j < 32; j += 8)
        tbuf[j][tx] = src[(size_t)(y0 + j) * 2048 + x0 + tx];
    __syncthreads();
#pragma unroll
    for (int j = ty; j < 32; j += 8) {
        const float v = tbuf[tx][j];
        __nv_bfloat16 h, l; split_bf16(v, h, l);
        const size_t idx = (size_t)(x0 + j) * 2048 + y0 + tx;
        dh[idx] = h; dl[idx] = l;
    }
}

__global__ void k_prep_x(const float* __restrict__ x)
{
    const size_t i = ((size_t)blockIdx.x * 256 + threadIdx.x) * 4;
    const float4 v = *(const float4*)(x + i);
    __nv_bfloat16 h[4], l[4];
    split_bf16(v.x, h[0], l[0]); split_bf16(v.y, h[1], l[1]);
    split_bf16(v.z, h[2], l[2]); split_bf16(v.w, h[3], l[3]);
    *(uint2*)(g_xh + i) = *(uint2*)h;
    *(uint2*)(g_xl + i) = *(uint2*)l;
}

__global__ void __launch_bounds__(256) k_rmsnorm(const float* __restrict__ qs,
                                                 const float* __restrict__ ks)
{
    const int gg   = blockIdx.x * 8 + (threadIdx.x >> 5);
    const int lane = threadIdx.x & 31;
    const float* tp = (blockIdx.y == 0) ? g_q : g_k;
    const float* sc = (blockIdx.y == 0) ? qs : ks;
    __nv_bfloat16* oh = (blockIdx.y == 0) ? g_qnh : g_knh;
    __nv_bfloat16* ol = (blockIdx.y == 0) ? g_qnl : g_knl;

    float4 v = *((const float4*)(tp + (size_t)gg * 128) + lane);
    float ss = v.x * v.x + v.y * v.y + v.z * v.z + v.w * v.w;
#pragma unroll
    for (int o = 16; o; o >>= 1) ss += __shfl_xor_sync(0xffffffffu, ss, o);
    const float r = rsqrtf(ss * (1.0f / 128.0f) + 1e-6f);
    const float4 s = *((const float4*)sc + lane);
    v.x *= r * s.x; v.y *= r * s.y; v.z *= r * s.z; v.w *= r * s.w;

    __nv_bfloat16 h[4], l[4];
    split_bf16(v.x, h[0], l[0]); split_bf16(v.y, h[1], l[1]);
    split_bf16(v.z, h[2], l[2]); split_bf16(v.w, h[3], l[3]);
    const size_t off = (size_t)gg * 128 + lane * 4;
    *(uint2*)(oh + off) = *(uint2*)h;
    *(uint2*)(ol + off) = *(uint2*)l;
}

__global__ void k_vt()
{
    __shared__ float tbuf[32][33];
    const int z = blockIdx.z, b = z >> 4, h = z & 15;
    const int s0 = blockIdx.x * 32, d0 = blockIdx.y * 32;
    const int tx = threadIdx.x, ty = threadIdx.y;
#pragma unroll
    for (int j = ty; j < 32; j += 8)
        tbuf[j][tx] = g_v[((size_t)b * S_ + s0 + j) * 2048 + h * 128 + d0 + tx];
    __syncthreads();
#pragma unroll
    for (int j = ty; j < 32; j += 8) {
        const float v = tbuf[tx][j];
        __nv_bfloat16 hh, ll; split_bf16(v, hh, ll);
        const size_t idx = (size_t)z * D_ * S_ + (size_t)(d0 + j) * S_ + s0 + tx;
        g_vth[idx] = hh; g_vtl[idx] = ll;
    }
}

__global__ void __launch_bounds__(256) k_softmax()
{
    const size_t rowoff = (size_t)blockIdx.x * S_;
    const float* p = g_p + rowoff;
    const int t = threadIdx.x, lane = t & 31, warp = t >> 5;
    __shared__ float red[8];

    float4 v0 = *((const float4*)p + t * 2);
    float4 v1 = *((const float4*)p + t * 2 + 1);

    float m = fmaxf(fmaxf(fmaxf(v0.x, v0.y), fmaxf(v0.z, v0.w)),
                    fmaxf(fmaxf(v1.x, v1.y), fmaxf(v1.z, v1.w)));
#pragma unroll
    for (int o = 16; o; o >>= 1) m = fmaxf(m, __shfl_xor_sync(0xffffffffu, m, o));
    if (lane == 0) red[warp] = m;
    __syncthreads();
    m = red[0];
#pragma unroll
    for (int i = 1; i < 8; i++) m = fmaxf(m, red[i]);
    __syncthreads();

    v0.x = __expf(v0.x - m); v0.y = __expf(v0.y - m);
    v0.z = __expf(v0.z - m); v0.w = __expf(v0.w - m);
    v1.x = __expf(v1.x - m); v1.y = __expf(v1.y - m);
    v1.z = __expf(v1.z - m); v1.w = __expf(v1.w - m);

    float s = v0.x + v0.y + v0.z + v0.w + v1.x + v1.y + v1.z + v1.w;
#pragma unroll
    for (int o = 16; o; o >>= 1) s += __shfl_xor_sync(0xffffffffu, s, o);
    if (lane == 0) red[warp] = s;
    __syncthreads();
    s = red[0];
#pragma unroll
    for (int i = 1; i < 8; i++) s += red[i];

    const float inv = 1.0f / s;
    float e[8] = {v0.x*inv, v0.y*inv, v0.z*inv, v0.w*inv,
                  v1.x*inv, v1.y*inv, v1.z*inv, v1.w*inv};
    __nv_bfloat16 h[8], l[8];
#pragma unroll
    for (int i = 0; i < 8; i++) split_bf16(e[i], h[i], l[i]);
    *(uint4*)(g_ph + rowoff + t * 8) = *(uint4*)h;
    *(uint4*)(g_pl + rowoff + t * 8) = *(uint4*)l;
}

__global__ void k_cvt_ao()
{
    const size_t i = ((size_t)blockIdx.x * 256 + threadIdx.x) * 4;
    const float4 v = *(const float4*)(g_ao + i);
    __nv_bfloat16 h[4], l[4];
    split_bf16(v.x, h[0], l[0]); split_bf16(v.y, h[1], l[1]);
    split_bf16(v.z, h[2], l[2]); split_bf16(v.w, h[3], l[3]);
    *(uint2*)(g_aoh + i) = *(uint2*)h;
    *(uint2*)(g_aol + i) = *(uint2*)l;
}

// ---------------------------------------------------------------------------
extern "C" void kernel_launch(void* const* d_in, const int* in_sizes, int n_in,
                              void* d_out, int out_size)
{
    const float* x  = (const float*)d_in[0];
    const float* wq = (const float*)d_in[1];
    const float* wk = (const float*)d_in[2];
    const float* wv = (const float*)d_in[3];
    const float* wo = (const float*)d_in[4];
    const float* wo_ = wo;
    const float* qs = (const float*)d_in[5];
    const float* ks = (const float*)d_in[6];
    float* out = (float*)d_out;

    constexpr int SMEM = 2 * 65536 + 1024;   // 132096
    cudaFuncSetAttribute(kg_proj,   cudaFuncAttributeMaxDynamicSharedMemorySize, SMEM);
    cudaFuncSetAttribute(kg_scores, cudaFuncAttributeMaxDynamicSharedMemorySize, SMEM);
    cudaFuncSetAttribute(kg_av,     cudaFuncAttributeMaxDynamicSharedMemorySize, SMEM);
    cudaFuncSetAttribute(kg_out,    cudaFuncAttributeMaxDynamicSharedMemorySize, SMEM);

    k_prep_w <<<dim3(64, 64, 4), dim3(32, 8)>>>(wq, wk, wv, wo_);
    k_prep_x <<<8192, 256>>>(x);
    kg_proj  <<<dim3(16, 32, 3), 256, SMEM>>>();
    k_rmsnorm<<<dim3(8192, 2), 256>>>(qs, ks);
    k_vt     <<<dim3(64, 4, 32), dim3(32, 8)>>>();
    kg_scores<<<dim3(16, 16, 32), 256, SMEM>>>();
    k_softmax<<<65536, 256>>>();
    kg_av    <<<dim3(16, 32), 256, SMEM>>>();
    k_cvt_ao <<<8192, 256>>>();
    kg_out   <<<dim3(16, 32), 256, SMEM>>>(out);
}

// round 5
// speedup vs baseline: 3.0552x; 1.0717x over previous
#include <cuda_runtime.h>
#include <cuda_bf16.h>
#include <cstdint>

#define B_  2
#define S_  2048
#define E_  2048
#define H_  16
#define D_  128
#define M_  (B_ * S_)     // 4096
#define HD  2048

// ---------------------------------------------------------------------------
// Scratch (device globals — allocation-free per harness rules)
// ---------------------------------------------------------------------------
__device__ float g_q [(size_t)M_ * HD];                    // fp32 [B,S,H,D]
__device__ float g_k [(size_t)M_ * HD];
__device__ float g_v [(size_t)M_ * HD];

__device__ __nv_bfloat16 g_xh [(size_t)M_ * E_],  g_xl [(size_t)M_ * E_];
__device__ __nv_bfloat16 g_wqh[(size_t)HD * E_],  g_wql[(size_t)HD * E_];   // [n][k]
__device__ __nv_bfloat16 g_wkh[(size_t)HD * E_],  g_wkl[(size_t)HD * E_];
__device__ __nv_bfloat16 g_wvh[(size_t)HD * E_],  g_wvl[(size_t)HD * E_];
__device__ __nv_bfloat16 g_woh[(size_t)E_ * HD],  g_wol[(size_t)E_ * HD];   // [n][k]
__device__ __nv_bfloat16 g_qnh[(size_t)M_ * HD],  g_qnl[(size_t)M_ * HD];
__device__ __nv_bfloat16 g_knh[(size_t)M_ * HD],  g_knl[(size_t)M_ * HD];
__device__ __nv_bfloat16 g_vth[(size_t)B_*H_*D_*S_], g_vtl[(size_t)B_*H_*D_*S_]; // [z][d][s]
__device__ __nv_bfloat16 g_aoh[(size_t)M_ * HD],  g_aol[(size_t)M_ * HD];

// ---------------------------------------------------------------------------
// helpers
// ---------------------------------------------------------------------------
__device__ __forceinline__ void cpa16(uint32_t dst, const void* src) {
    asm volatile("cp.async.cg.shared.global [%0], [%1], 16;\n" :: "r"(dst), "l"(src));
}
#define CP_COMMIT() asm volatile("cp.async.commit_group;\n" ::: "memory")
template <int N>
__device__ __forceinline__ void cp_wait() {
    asm volatile("cp.async.wait_group %0;\n" :: "n"(N) : "memory");
}
#define LDMX4(r, a) \
    asm volatile("ldmatrix.sync.aligned.m8n8.x4.shared.b16 {%0,%1,%2,%3}, [%4];" \
        : "=r"((r)[0]), "=r"((r)[1]), "=r"((r)[2]), "=r"((r)[3]) : "r"(a))
#define LDMX2(r, a) \
    asm volatile("ldmatrix.sync.aligned.m8n8.x2.shared.b16 {%0,%1}, [%2];" \
        : "=r"((r)[0]), "=r"((r)[1]) : "r"(a))

__device__ __forceinline__ void mma_bf16(float* c, const uint32_t* a, const uint32_t* b) {
    asm volatile(
        "mma.sync.aligned.m16n8k16.row.col.f32.bf16.bf16.f32 "
        "{%0,%1,%2,%3},{%4,%5,%6,%7},{%8,%9},{%0,%1,%2,%3};"
        : "+f"(c[0]), "+f"(c[1]), "+f"(c[2]), "+f"(c[3])
        : "r"(a[0]), "r"(a[1]), "r"(a[2]), "r"(a[3]), "r"(b[0]), "r"(b[1]));
}

__device__ __forceinline__ void split_bf16(float x, __nv_bfloat16& h, __nv_bfloat16& l) {
    h = __float2bfloat16_rn(x);
    l = __float2bfloat16_rn(x - __bfloat162float(h));
}
__device__ __forceinline__ uint32_t pack2(__nv_bfloat16 a, __nv_bfloat16 b) {
    __nv_bfloat162 v; v.x = a; v.y = b;
    return *(uint32_t*)&v;
}

// ---------------------------------------------------------------------------
// 128x128 CTA tile bf16 3-term GEMM (unchanged from R4)
// ---------------------------------------------------------------------------
__device__ __forceinline__ void gemm_bf3(const __nv_bfloat16* __restrict__ Ah,
                                         const __nv_bfloat16* __restrict__ Al,
                                         const __nv_bfloat16* __restrict__ Bh,
                                         const __nv_bfloat16* __restrict__ Bl,
                                         float* __restrict__ C, int K)
{
    extern __shared__ char dsm[];
    const uint32_t s0 = ((uint32_t)__cvta_generic_to_shared(dsm) + 1023) & ~1023u;

    const int tid  = threadIdx.x;
    const int warp = tid >> 5;
    const int lane = tid & 31;
    const int g    = lane >> 2;
    const int t    = lane & 3;
    const int m0w  = (warp & 1) * 64;
    const int n0w  = (warp >> 1) * 32;

    const __nv_bfloat16* srcs[4] = {Ah, Al, Bh, Bl};

    float acc[4][4][4];
#pragma unroll
    for (int i = 0; i < 4; i++)
#pragma unroll
        for (int j = 0; j < 4; j++)
#pragma unroll
            for (int e = 0; e < 4; e++) acc[i][j][e] = 0.0f;

    const int nch = K >> 6;

    auto issue = [&](int c) {
        const uint32_t stb = s0 + (uint32_t)(c & 1) * 65536u;
        const int kt = c * 64;
#pragma unroll
        for (int arr = 0; arr < 4; arr++) {
            const __nv_bfloat16* sp = srcs[arr];
            const uint32_t ab = stb + (uint32_t)arr * 16384u;
#pragma unroll
            for (int j = 0; j < 4; j++) {
                const int loc = tid + j * 256;
                const int row = loc >> 3;
                const int ch  = loc & 7;
                const uint32_t off = (uint32_t)row * 128u
                                   + (uint32_t)((ch ^ (row & 7)) << 4);
                cpa16(ab + off, sp + (size_t)row * 2048 + kt + ch * 8);
            }
        }
        CP_COMMIT();
    };

    issue(0);

    for (int c = 0; c < nch; c++) {
        if (c + 1 < nch) { issue(c + 1); cp_wait<1>(); }
        else             { cp_wait<0>(); }
        __syncthreads();

        const uint32_t stb = s0 + (uint32_t)(c & 1) * 65536u;
        const uint32_t aB  = stb;
        const uint32_t bB  = stb + 32768u;

#pragma unroll
        for (int ks = 0; ks < 4; ks++) {
            uint32_t bh[4][2], bl[4][2];
#pragma unroll
            for (int nt = 0; nt < 4; nt++) {
                const int rb = n0w + nt * 8 + (lane & 7);
                const int cb = ks * 2 + ((lane >> 3) & 1);
                const uint32_t off = (uint32_t)rb * 128u
                                   + (uint32_t)((cb ^ (rb & 7)) << 4);
                LDMX2(bh[nt], bB + off);
                LDMX2(bl[nt], bB + 16384u + off);
            }
#pragma unroll
            for (int mt = 0; mt < 4; mt++) {
                const int ra = m0w + mt * 16 + (lane & 15);
                const int ca = ks * 2 + (lane >> 4);
                const uint32_t off = (uint32_t)ra * 128u
                                   + (uint32_t)((ca ^ (ra & 7)) << 4);
                uint32_t ah[4], al[4];
                LDMX4(ah, aB + off);
                LDMX4(al, aB + 16384u + off);
#pragma unroll
                for (int nt = 0; nt < 4; nt++) {
                    mma_bf16(acc[mt][nt], ah, bh[nt]);
                    mma_bf16(acc[mt][nt], ah, bl[nt]);
                    mma_bf16(acc[mt][nt], al, bh[nt]);
                }
            }
        }
        __syncthreads();
    }

#pragma unroll
    for (int mt = 0; mt < 4; mt++) {
#pragma unroll
        for (int nt = 0; nt < 4; nt++) {
            const int r0 = m0w + mt * 16 + g;
            const int c0 = n0w + nt * 8 + 2 * t;
            *(float2*)(C + (size_t)r0 * 2048 + c0) =
                make_float2(acc[mt][nt][0], acc[mt][nt][1]);
            *(float2*)(C + (size_t)(r0 + 8) * 2048 + c0) =
                make_float2(acc[mt][nt][2], acc[mt][nt][3]);
        }
    }
}

__global__ void __launch_bounds__(256, 1) kg_proj()
{
    const int z = blockIdx.z;
    const __nv_bfloat16* wh = (z == 0) ? g_wqh : (z == 1) ? g_wkh : g_wvh;
    const __nv_bfloat16* wl = (z == 0) ? g_wql : (z == 1) ? g_wkl : g_wvl;
    float* o = (z == 0) ? g_q : (z == 1) ? g_k : g_v;
    const size_t ao = (size_t)blockIdx.y * 128 * 2048;
    const size_t bo = (size_t)blockIdx.x * 128 * 2048;
    gemm_bf3(g_xh + ao, g_xl + ao, wh + bo, wl + bo,
             o + ao + blockIdx.x * 128, E_);
}

__global__ void __launch_bounds__(256, 1) kg_out(float* out)
{
    const size_t ao = (size_t)blockIdx.y * 128 * 2048;
    const size_t bo = (size_t)blockIdx.x * 128 * 2048;
    gemm_bf3(g_aoh + ao, g_aol + ao, g_woh + bo, g_wol + bo,
             out + ao + blockIdx.x * 128, HD);
}

// ---------------------------------------------------------------------------
// Flash attention: per (q-tile 128, b, h). 256 thr, 8 warps x 16 rows.
// SMEM: Q hi/lo 64KB | 2 stages x (K hi/lo 32KB + V^T hi/lo 32KB) | P hi/lo 32KB
// ---------------------------------------------------------------------------
#define FL_SMEM 230400

__global__ void __launch_bounds__(256, 1) k_flash()
{
    extern __shared__ char dsm[];
    const uint32_t s0 = ((uint32_t)__cvta_generic_to_shared(dsm) + 1023) & ~1023u;
    const uint32_t PH = s0 + 196608u, PL = PH + 16384u;

    const int qt = blockIdx.x, z = blockIdx.y, b = z >> 4, h = z & 15;
    const int tid = threadIdx.x, warp = tid >> 5, lane = tid & 31;
    const int g = lane >> 2, t = lane & 3;

    // ---- Q load (once): 2 splits x 2 planes x 128 rows x 8 chunks
    {
        const __nv_bfloat16* qsrc[2] = {g_qnh, g_qnl};
#pragma unroll
        for (int sp = 0; sp < 2; sp++) {
            const uint32_t db = s0 + (uint32_t)sp * 32768u;
#pragma unroll
            for (int j = 0; j < 8; j++) {
                const int i = tid + j * 256;          // 0..2047
                const int pl = i >> 10, row = (i >> 3) & 127, ch = i & 7;
                cpa16(db + pl * 16384u + row * 128u + ((ch ^ (row & 7)) << 4),
                      qsrc[sp] + ((size_t)(b * S_ + qt * 128 + row)) * 2048
                               + h * 128 + pl * 64 + ch * 8);
            }
        }
    }

    auto issue_kv = [&](int it) {
        const uint32_t stb = s0 + 65536u + (uint32_t)(it & 1) * 65536u;
        const int kt = it * 64;
        const __nv_bfloat16* ksrc[2] = {g_knh, g_knl};
        const __nv_bfloat16* vsrc[2] = {g_vth, g_vtl};
#pragma unroll
        for (int sp = 0; sp < 2; sp++) {
            const uint32_t kb = stb + (uint32_t)sp * 16384u;
#pragma unroll
            for (int j = 0; j < 4; j++) {
                const int i = tid + j * 256;          // 0..1023
                const int pl = i >> 9, row = (i >> 3) & 63, ch = i & 7;
                cpa16(kb + pl * 8192u + row * 128u + ((ch ^ (row & 7)) << 4),
                      ksrc[sp] + ((size_t)(b * S_ + kt + row)) * 2048
                               + h * 128 + pl * 64 + ch * 8);
            }
            const uint32_t vb = stb + 32768u + (uint32_t)sp * 16384u;
#pragma unroll
            for (int j = 0; j < 4; j++) {
                const int i = tid + j * 256;
                const int row = i >> 3, ch = i & 7;   // row = d, col = key
                cpa16(vb + row * 128u + ((ch ^ (row & 7)) << 4),
                      vsrc[sp] + (size_t)z * D_ * S_ + (size_t)row * S_
                               + kt + ch * 8);
            }
        }
        CP_COMMIT();
    };

    issue_kv(0);   // commits Q + stage0 together

    float oacc[16][4];
#pragma unroll
    for (int i = 0; i < 16; i++)
#pragma unroll
        for (int e = 0; e < 4; e++) oacc[i][e] = 0.0f;
    float mprev0 = -1e30f, mprev1 = -1e30f, lsum0 = 0.0f, lsum1 = 0.0f;

    for (int it = 0; it < 32; it++) {
        if (it + 1 < 32) { issue_kv(it + 1); cp_wait<1>(); }
        else             { cp_wait<0>(); }
        __syncthreads();

        const uint32_t stb = s0 + 65536u + (uint32_t)(it & 1) * 65536u;

        // ---- S = Qn Kn^T (3-term), 16 rows x 64 keys per warp
        float sacc[8][4];
#pragma unroll
        for (int i = 0; i < 8; i++)
#pragma unroll
            for (int e = 0; e < 4; e++) sacc[i][e] = 0.0f;

#pragma unroll
        for (int p = 0; p < 2; p++) {
            const uint32_t qh = s0 + p * 16384u;
            const uint32_t ql = s0 + 32768u + p * 16384u;
            const uint32_t kh = stb + p * 8192u;
            const uint32_t kl = stb + 16384u + p * 8192u;
#pragma unroll
            for (int ks = 0; ks < 4; ks++) {
                const int ra = warp * 16 + (lane & 15);
                const int ca = ks * 2 + (lane >> 4);
                const uint32_t offA = ra * 128u + ((ca ^ (ra & 7)) << 4);
                uint32_t ah[4], al[4];
                LDMX4(ah, qh + offA);
                LDMX4(al, ql + offA);
#pragma unroll
                for (int np = 0; np < 4; np++) {
                    const int rb = np * 16 + (lane & 15);
                    const int cb = ks * 2 + (lane >> 4);
                    const uint32_t offB = rb * 128u + ((cb ^ (rb & 7)) << 4);
                    uint32_t b4h[4], b4l[4];
                    LDMX4(b4h, kh + offB);
                    LDMX4(b4l, kl + offB);
                    uint32_t be[2] = {b4h[0], b4h[2]};
                    uint32_t bo[2] = {b4h[1], b4h[3]};
                    uint32_t le[2] = {b4l[0], b4l[2]};
                    uint32_t lo[2] = {b4l[1], b4l[3]};
                    mma_bf16(sacc[2*np],   ah, be);
                    mma_bf16(sacc[2*np],   ah, le);
                    mma_bf16(sacc[2*np],   al, be);
                    mma_bf16(sacc[2*np+1], ah, bo);
                    mma_bf16(sacc[2*np+1], ah, lo);
                    mma_bf16(sacc[2*np+1], al, bo);
                }
            }
        }

        // ---- online softmax (rows g and g+8 of the warp's 16)
        float mx0 = -1e30f, mx1 = -1e30f;
#pragma unroll
        for (int i = 0; i < 8; i++) {
            mx0 = fmaxf(mx0, fmaxf(sacc[i][0], sacc[i][1]));
            mx1 = fmaxf(mx1, fmaxf(sacc[i][2], sacc[i][3]));
        }
        mx0 = fmaxf(mx0, __shfl_xor_sync(0xffffffffu, mx0, 1));
        mx0 = fmaxf(mx0, __shfl_xor_sync(0xffffffffu, mx0, 2));
        mx1 = fmaxf(mx1, __shfl_xor_sync(0xffffffffu, mx1, 1));
        mx1 = fmaxf(mx1, __shfl_xor_sync(0xffffffffu, mx1, 2));

        const float mn0 = fmaxf(mprev0, mx0);
        const float mn1 = fmaxf(mprev1, mx1);
        const float sc0 = __expf(mprev0 - mn0);
        const float sc1 = __expf(mprev1 - mn1);
        mprev0 = mn0; mprev1 = mn1;

        float su0 = 0.0f, su1 = 0.0f;
#pragma unroll
        for (int i = 0; i < 8; i++) {
            sacc[i][0] = __expf(sacc[i][0] - mn0);
            sacc[i][1] = __expf(sacc[i][1] - mn0);
            sacc[i][2] = __expf(sacc[i][2] - mn1);
            sacc[i][3] = __expf(sacc[i][3] - mn1);
            su0 += sacc[i][0] + sacc[i][1];
            su1 += sacc[i][2] + sacc[i][3];
        }
        su0 += __shfl_xor_sync(0xffffffffu, su0, 1);
        su0 += __shfl_xor_sync(0xffffffffu, su0, 2);
        su1 += __shfl_xor_sync(0xffffffffu, su1, 1);
        su1 += __shfl_xor_sync(0xffffffffu, su1, 2);
        lsum0 = lsum0 * sc0 + su0;
        lsum1 = lsum1 * sc1 + su1;

#pragma unroll
        for (int i = 0; i < 16; i++) {
            oacc[i][0] *= sc0; oacc[i][1] *= sc0;
            oacc[i][2] *= sc1; oacc[i][3] *= sc1;
        }

        // ---- store P hi/lo to SMEM (A-operand layout)
#pragma unroll
        for (int nt = 0; nt < 8; nt++) {
#pragma unroll
            for (int r = 0; r < 2; r++) {
                const float v0 = sacc[nt][2*r], v1 = sacc[nt][2*r+1];
                __nv_bfloat16 h0, l0, h1, l1;
                split_bf16(v0, h0, l0); split_bf16(v1, h1, l1);
                const int row = warp * 16 + g + r * 8;
                const uint32_t off = row * 128u + ((nt ^ (row & 7)) << 4) + t * 4u;
                *(uint32_t*)(dsm + (PH + off - (uint32_t)__cvta_generic_to_shared(dsm))) = pack2(h0, h1);
                *(uint32_t*)(dsm + (PL + off - (uint32_t)__cvta_generic_to_shared(dsm))) = pack2(l0, l1);
            }
        }
        __syncwarp();

        // ---- O += P V (3-term); V^T rows = d (n), cols = key (k)
        const uint32_t vh = stb + 32768u;
        const uint32_t vl = stb + 49152u;
#pragma unroll
        for (int ks = 0; ks < 4; ks++) {
            const int ra = warp * 16 + (lane & 15);
            const int ca = ks * 2 + (lane >> 4);
            const uint32_t offA = ra * 128u + ((ca ^ (ra & 7)) << 4);
            uint32_t ph_[4], pl_[4];
            LDMX4(ph_, PH + offA);
            LDMX4(pl_, PL + offA);
#pragma unroll
            for (int np = 0; np < 8; np++) {
                const int rb = np * 16 + (lane & 15);
                const int cb = ks * 2 + (lane >> 4);
                const uint32_t offB = rb * 128u + ((cb ^ (rb & 7)) << 4);
                uint32_t v4h[4], v4l[4];
                LDMX4(v4h, vh + offB);
                LDMX4(v4l, vl + offB);
                uint32_t be[2] = {v4h[0], v4h[2]};
                uint32_t bo[2] = {v4h[1], v4h[3]};
                uint32_t le[2] = {v4l[0], v4l[2]};
                mma_bf16(oacc[2*np],   ph_, be);
                mma_bf16(oacc[2*np],   ph_, le);
                mma_bf16(oacc[2*np],   pl_, be);
                mma_bf16(oacc[2*np+1], ph_, bo);
                uint32_t lo2[2] = {v4l[1], v4l[3]};
                mma_bf16(oacc[2*np+1], ph_, lo2);
                mma_bf16(oacc[2*np+1], pl_, bo);
            }
        }
        __syncthreads();   // protect stage buffers before next issue
    }

    // ---- epilogue: O / l -> bf16 hi/lo splits
    const float inv0 = 1.0f / lsum0, inv1 = 1.0f / lsum1;
    const int row0 = b * S_ + qt * 128 + warp * 16 + g;
#pragma unroll
    for (int nt = 0; nt < 16; nt++) {
        const int col = h * 128 + nt * 8 + 2 * t;
        {
            const float o0 = oacc[nt][0] * inv0, o1 = oacc[nt][1] * inv0;
            __nv_bfloat16 h0, l0, h1, l1;
            split_bf16(o0, h0, l0); split_bf16(o1, h1, l1);
            *(uint32_t*)(g_aoh + (size_t)row0 * 2048 + col) = pack2(h0, h1);
            *(uint32_t*)(g_aol + (size_t)row0 * 2048 + col) = pack2(l0, l1);
        }
        {
            const float o0 = oacc[nt][2] * inv1, o1 = oacc[nt][3] * inv1;
            __nv_bfloat16 h0, l0, h1, l1;
            split_bf16(o0, h0, l0); split_bf16(o1, h1, l1);
            *(uint32_t*)(g_aoh + (size_t)(row0 + 8) * 2048 + col) = pack2(h0, h1);
            *(uint32_t*)(g_aol + (size_t)(row0 + 8) * 2048 + col) = pack2(l0, l1);
        }
    }
}

// ---------------------------------------------------------------------------
// Prep / conversion kernels
// ---------------------------------------------------------------------------
__global__ void k_prep_w(const float* __restrict__ wq, const float* __restrict__ wk,
                         const float* __restrict__ wv, const float* __restrict__ wo)
{
    __shared__ float tbuf[32][33];
    const int z = blockIdx.z;
    const float* src = (z == 0) ? wq : (z == 1) ? wk : (z == 2) ? wv : wo;
    __nv_bfloat16* dh = (z == 0) ? g_wqh : (z == 1) ? g_wkh : (z == 2) ? g_wvh : g_woh;
    __nv_bfloat16* dl = (z == 0) ? g_wql : (z == 1) ? g_wkl : (z == 2) ? g_wvl : g_wol;
    const int x0 = blockIdx.x * 32, y0 = blockIdx.y * 32;
    const int tx = threadIdx.x, ty = threadIdx.y;
#pragma unroll
    for (int j = ty; j < 32; j += 8)
        tbuf[j][tx] = src[(size_t)(y0 + j) * 2048 + x0 + tx];
    __syncthreads();
#pragma unroll
    for (int j = ty; j < 32; j += 8) {
        const float v = tbuf[tx][j];
        __nv_bfloat16 h, l; split_bf16(v, h, l);
        const size_t idx = (size_t)(x0 + j) * 2048 + y0 + tx;
        dh[idx] = h; dl[idx] = l;
    }
}

__global__ void k_prep_x(const float* __restrict__ x)
{
    const size_t i = ((size_t)blockIdx.x * 256 + threadIdx.x) * 4;
    const float4 v = *(const float4*)(x + i);
    __nv_bfloat16 h[4], l[4];
    split_bf16(v.x, h[0], l[0]); split_bf16(v.y, h[1], l[1]);
    split_bf16(v.z, h[2], l[2]); split_bf16(v.w, h[3], l[3]);
    *(uint2*)(g_xh + i) = *(uint2*)h;
    *(uint2*)(g_xl + i) = *(uint2*)l;
}

__global__ void __launch_bounds__(256) k_rmsnorm(const float* __restrict__ qs,
                                                 const float* __restrict__ ks)
{
    const int gg   = blockIdx.x * 8 + (threadIdx.x >> 5);
    const int lane = threadIdx.x & 31;
    const float* tp = (blockIdx.y == 0) ? g_q : g_k;
    const float* sc = (blockIdx.y == 0) ? qs : ks;
    __nv_bfloat16* oh = (blockIdx.y == 0) ? g_qnh : g_knh;
    __nv_bfloat16* ol = (blockIdx.y == 0) ? g_qnl : g_knl;

    float4 v = *((const float4*)(tp + (size_t)gg * 128) + lane);
    float ss = v.x * v.x + v.y * v.y + v.z * v.z + v.w * v.w;
#pragma unroll
    for (int o = 16; o; o >>= 1) ss += __shfl_xor_sync(0xffffffffu, ss, o);
    const float r = rsqrtf(ss * (1.0f / 128.0f) + 1e-6f);
    const float4 s = *((const float4*)sc + lane);
    v.x *= r * s.x; v.y *= r * s.y; v.z *= r * s.z; v.w *= r * s.w;

    __nv_bfloat16 h[4], l[4];
    split_bf16(v.x, h[0], l[0]); split_bf16(v.y, h[1], l[1]);
    split_bf16(v.z, h[2], l[2]); split_bf16(v.w, h[3], l[3]);
    const size_t off = (size_t)gg * 128 + lane * 4;
    *(uint2*)(oh + off) = *(uint2*)h;
    *(uint2*)(ol + off) = *(uint2*)l;
}

__global__ void k_vt()
{
    __shared__ float tbuf[32][33];
    const int z = blockIdx.z, b = z >> 4, h = z & 15;
    const int s0 = blockIdx.x * 32, d0 = blockIdx.y * 32;
    const int tx = threadIdx.x, ty = threadIdx.y;
#pragma unroll
    for (int j = ty; j < 32; j += 8)
        tbuf[j][tx] = g_v[((size_t)b * S_ + s0 + j) * 2048 + h * 128 + d0 + tx];
    __syncthreads();
#pragma unroll
    for (int j = ty; j < 32; j += 8) {
        const float v = tbuf[tx][j];
        __nv_bfloat16 hh, ll; split_bf16(v, hh, ll);
        const size_t idx = (size_t)z * D_ * S_ + (size_t)(d0 + j) * S_ + s0 + tx;
        g_vth[idx] = hh; g_vtl[idx] = ll;
    }
}

// ---------------------------------------------------------------------------
extern "C" void kernel_launch(void* const* d_in, const int* in_sizes, int n_in,
                              void* d_out, int out_size)
{
    const float* x  = (const float*)d_in[0];
    const float* wq = (const float*)d_in[1];
    const float* wk = (const float*)d_in[2];
    const float* wv = (const float*)d_in[3];
    const float* wo = (const float*)d_in[4];
    const float* qs = (const float*)d_in[5];
    const float* ks = (const float*)d_in[6];
    float* out = (float*)d_out;

    constexpr int SMEM = 2 * 65536 + 1024;   // gemm_bf3: 132096
    cudaFuncSetAttribute(kg_proj, cudaFuncAttributeMaxDynamicSharedMemorySize, SMEM);
    cudaFuncSetAttribute(kg_out,  cudaFuncAttributeMaxDynamicSharedMemorySize, SMEM);
    cudaFuncSetAttribute(k_flash, cudaFuncAttributeMaxDynamicSharedMemorySize, FL_SMEM);

    k_prep_w <<<dim3(64, 64, 4), dim3(32, 8)>>>(wq, wk, wv, wo);
    k_prep_x <<<8192, 256>>>(x);
    kg_proj  <<<dim3(16, 32, 3), 256, SMEM>>>();
    k_rmsnorm<<<dim3(8192, 2), 256>>>(qs, ks);
    k_vt     <<<dim3(64, 4, 32), dim3(32, 8)>>>();
    k_flash  <<<dim3(16, 32), 256, FL_SMEM>>>();
    kg_out   <<<dim3(16, 32), 256, SMEM>>>(out);
}

// round 7
// speedup vs baseline: 3.6101x; 1.1816x over previous
#include <cuda_runtime.h>
#include <cuda_fp16.h>
#include <cstdint>

#define B_  2
#define S_  2048
#define E_  2048
#define H_  16
#define D_  128
#define M_  (B_ * S_)     // 4096
#define HD  2048

// ---------------------------------------------------------------------------
// Scratch (device globals — allocation-free per harness rules)
// ---------------------------------------------------------------------------
__device__ float g_q [(size_t)M_ * HD];                    // fp32 [B,S,H,D]
__device__ float g_k [(size_t)M_ * HD];
__device__ float g_v [(size_t)M_ * HD];

__device__ __half g_xh [(size_t)M_ * E_],  g_xl [(size_t)M_ * E_];   // x split
__device__ __half g_wqh[(size_t)HD * E_],  g_wql[(size_t)HD * E_];   // wq split [n][k]
__device__ __half g_wkh[(size_t)HD * E_],  g_wkl[(size_t)HD * E_];   // wk split
__device__ __half g_wvh[(size_t)HD * E_];                            // wv single
__device__ __half g_woh[(size_t)E_ * HD];                            // wo single
__device__ __half g_qnh[(size_t)M_ * HD],  g_qnl[(size_t)M_ * HD];   // qn split
__device__ __half g_knh[(size_t)M_ * HD],  g_knl[(size_t)M_ * HD];   // kn split
__device__ __half g_vth[(size_t)B_*H_*D_*S_];                        // V^T single [z][d][s]
__device__ __half g_aoh[(size_t)M_ * HD],  g_aol[(size_t)M_ * HD];   // ao split

// ---------------------------------------------------------------------------
// helpers
// ---------------------------------------------------------------------------
__device__ __forceinline__ void cpa16(uint32_t dst, const void* src) {
    asm volatile("cp.async.cg.shared.global [%0], [%1], 16;\n" :: "r"(dst), "l"(src));
}
#define CP_COMMIT() asm volatile("cp.async.commit_group;\n" ::: "memory")
template <int N>
__device__ __forceinline__ void cp_wait() {
    asm volatile("cp.async.wait_group %0;\n" :: "n"(N) : "memory");
}
#define LDMX4(r, a) \
    asm volatile("ldmatrix.sync.aligned.m8n8.x4.shared.b16 {%0,%1,%2,%3}, [%4];" \
        : "=r"((r)[0]), "=r"((r)[1]), "=r"((r)[2]), "=r"((r)[3]) : "r"(a))
#define LDMX2(r, a) \
    asm volatile("ldmatrix.sync.aligned.m8n8.x2.shared.b16 {%0,%1}, [%2];" \
        : "=r"((r)[0]), "=r"((r)[1]) : "r"(a))

__device__ __forceinline__ void mma_f16(float* c, const uint32_t* a, const uint32_t* b) {
    asm volatile(
        "mma.sync.aligned.m16n8k16.row.col.f32.f16.f16.f32 "
        "{%0,%1,%2,%3},{%4,%5,%6,%7},{%8,%9},{%0,%1,%2,%3};"
        : "+f"(c[0]), "+f"(c[1]), "+f"(c[2]), "+f"(c[3])
        : "r"(a[0]), "r"(a[1]), "r"(a[2]), "r"(a[3]), "r"(b[0]), "r"(b[1]));
}

__device__ __forceinline__ void split_h(float x, __half& h, __half& l) {
    h = __float2half_rn(x);
    l = __float2half_rn(x - __half2float(h));
}
__device__ __forceinline__ uint32_t pack2h(__half a, __half b) {
    __half2 v; v.x = a; v.y = b;
    return *(uint32_t*)&v;
}

// ---------------------------------------------------------------------------
// fp16 2-term GEMM: C = (Ah+Al)[128,K] * B[128,K]^T. 48KB/stage x2.
// ---------------------------------------------------------------------------
__device__ __forceinline__ void gemm_f16(const __half* __restrict__ Ah,
                                         const __half* __restrict__ Al,
                                         const __half* __restrict__ Bh,
                                         float* __restrict__ C, int K)
{
    extern __shared__ char dsm[];
    const uint32_t s0 = ((uint32_t)__cvta_generic_to_shared(dsm) + 1023) & ~1023u;

    const int tid  = threadIdx.x;
    const int warp = tid >> 5;
    const int lane = tid & 31;
    const int g    = lane >> 2;
    const int t    = lane & 3;
    const int m0w  = (warp & 1) * 64;
    const int n0w  = (warp >> 1) * 32;

    const __half* srcs[3] = {Ah, Al, Bh};

    float acc[4][4][4];
#pragma unroll
    for (int i = 0; i < 4; i++)
#pragma unroll
        for (int j = 0; j < 4; j++)
#pragma unroll
            for (int e = 0; e < 4; e++) acc[i][j][e] = 0.0f;

    const int nch = K >> 6;

    auto issue = [&](int c) {
        const uint32_t stb = s0 + (uint32_t)(c & 1) * 49152u;
        const int kt = c * 64;
#pragma unroll
        for (int arr = 0; arr < 3; arr++) {
            const __half* sp = srcs[arr];
            const uint32_t ab = stb + (uint32_t)arr * 16384u;
#pragma unroll
            for (int j = 0; j < 4; j++) {
                const int loc = tid + j * 256;
                const int row = loc >> 3;
                const int ch  = loc & 7;
                const uint32_t off = (uint32_t)row * 128u
                                   + (uint32_t)((ch ^ (row & 7)) << 4);
                cpa16(ab + off, sp + (size_t)row * 2048 + kt + ch * 8);
            }
        }
        CP_COMMIT();
    };

    issue(0);

    for (int c = 0; c < nch; c++) {
        if (c + 1 < nch) { issue(c + 1); cp_wait<1>(); }
        else             { cp_wait<0>(); }
        __syncthreads();

        const uint32_t stb = s0 + (uint32_t)(c & 1) * 49152u;
        const uint32_t aB  = stb;
        const uint32_t bB  = stb + 32768u;

#pragma unroll
        for (int ks = 0; ks < 4; ks++) {
            uint32_t bh[4][2];
#pragma unroll
            for (int nt = 0; nt < 4; nt++) {
                const int rb = n0w + nt * 8 + (lane & 7);
                const int cb = ks * 2 + ((lane >> 3) & 1);
                const uint32_t off = (uint32_t)rb * 128u
                                   + (uint32_t)((cb ^ (rb & 7)) << 4);
                LDMX2(bh[nt], bB + off);
            }
#pragma unroll
            for (int mt = 0; mt < 4; mt++) {
                const int ra = m0w + mt * 16 + (lane & 15);
                const int ca = ks * 2 + (lane >> 4);
                const uint32_t off = (uint32_t)ra * 128u
                                   + (uint32_t)((ca ^ (ra & 7)) << 4);
                uint32_t ah[4], al[4];
                LDMX4(ah, aB + off);
                LDMX4(al, aB + 16384u + off);
#pragma unroll
                for (int nt = 0; nt < 4; nt++) {
                    mma_f16(acc[mt][nt], ah, bh[nt]);
                    mma_f16(acc[mt][nt], al, bh[nt]);
                }
            }
        }
        __syncthreads();
    }

#pragma unroll
    for (int mt = 0; mt < 4; mt++) {
#pragma unroll
        for (int nt = 0; nt < 4; nt++) {
            const int r0 = m0w + mt * 16 + g;
            const int c0 = n0w + nt * 8 + 2 * t;
            *(float2*)(C + (size_t)r0 * 2048 + c0) =
                make_float2(acc[mt][nt][0], acc[mt][nt][1]);
            *(float2*)(C + (size_t)(r0 + 8) * 2048 + c0) =
                make_float2(acc[mt][nt][2], acc[mt][nt][3]);
        }
    }
}

// ---------------------------------------------------------------------------
// fp16 3-term GEMM: C = (Ah+Al)[128,K] * (Bh+Bl)[128,K]^T. 64KB/stage x2.
// ---------------------------------------------------------------------------
__device__ __forceinline__ void gemm_f16_3t(const __half* __restrict__ Ah,
                                            const __half* __restrict__ Al,
                                            const __half* __restrict__ Bh,
                                            const __half* __restrict__ Bl,
                                            float* __restrict__ C, int K)
{
    extern __shared__ char dsm[];
    const uint32_t s0 = ((uint32_t)__cvta_generic_to_shared(dsm) + 1023) & ~1023u;

    const int tid  = threadIdx.x;
    const int warp = tid >> 5;
    const int lane = tid & 31;
    const int g    = lane >> 2;
    const int t    = lane & 3;
    const int m0w  = (warp & 1) * 64;
    const int n0w  = (warp >> 1) * 32;

    const __half* srcs[4] = {Ah, Al, Bh, Bl};

    float acc[4][4][4];
#pragma unroll
    for (int i = 0; i < 4; i++)
#pragma unroll
        for (int j = 0; j < 4; j++)
#pragma unroll
            for (int e = 0; e < 4; e++) acc[i][j][e] = 0.0f;

    const int nch = K >> 6;

    auto issue = [&](int c) {
        const uint32_t stb = s0 + (uint32_t)(c & 1) * 65536u;
        const int kt = c * 64;
#pragma unroll
        for (int arr = 0; arr < 4; arr++) {
            const __half* sp = srcs[arr];
            const uint32_t ab = stb + (uint32_t)arr * 16384u;
#pragma unroll
            for (int j = 0; j < 4; j++) {
                const int loc = tid + j * 256;
                const int row = loc >> 3;
                const int ch  = loc & 7;
                const uint32_t off = (uint32_t)row * 128u
                                   + (uint32_t)((ch ^ (row & 7)) << 4);
                cpa16(ab + off, sp + (size_t)row * 2048 + kt + ch * 8);
            }
        }
        CP_COMMIT();
    };

    issue(0);

    for (int c = 0; c < nch; c++) {
        if (c + 1 < nch) { issue(c + 1); cp_wait<1>(); }
        else             { cp_wait<0>(); }
        __syncthreads();

        const uint32_t stb = s0 + (uint32_t)(c & 1) * 65536u;
        const uint32_t aB  = stb;              // Ah; Al +16384
        const uint32_t bB  = stb + 32768u;     // Bh; Bl +16384

#pragma unroll
        for (int ks = 0; ks < 4; ks++) {
            uint32_t bh[4][2], bl[4][2];
#pragma unroll
            for (int nt = 0; nt < 4; nt++) {
                const int rb = n0w + nt * 8 + (lane & 7);
                const int cb = ks * 2 + ((lane >> 3) & 1);
                const uint32_t off = (uint32_t)rb * 128u
                                   + (uint32_t)((cb ^ (rb & 7)) << 4);
                LDMX2(bh[nt], bB + off);
                LDMX2(bl[nt], bB + 16384u + off);
            }
#pragma unroll
            for (int mt = 0; mt < 4; mt++) {
                const int ra = m0w + mt * 16 + (lane & 15);
                const int ca = ks * 2 + (lane >> 4);
                const uint32_t off = (uint32_t)ra * 128u
                                   + (uint32_t)((ca ^ (ra & 7)) << 4);
                uint32_t ah[4], al[4];
                LDMX4(ah, aB + off);
                LDMX4(al, aB + 16384u + off);
#pragma unroll
                for (int nt = 0; nt < 4; nt++) {
                    mma_f16(acc[mt][nt], ah, bh[nt]);
                    mma_f16(acc[mt][nt], ah, bl[nt]);
                    mma_f16(acc[mt][nt], al, bh[nt]);
                }
            }
        }
        __syncthreads();
    }

#pragma unroll
    for (int mt = 0; mt < 4; mt++) {
#pragma unroll
        for (int nt = 0; nt < 4; nt++) {
            const int r0 = m0w + mt * 16 + g;
            const int c0 = n0w + nt * 8 + 2 * t;
            *(float2*)(C + (size_t)r0 * 2048 + c0) =
                make_float2(acc[mt][nt][0], acc[mt][nt][1]);
            *(float2*)(C + (size_t)(r0 + 8) * 2048 + c0) =
                make_float2(acc[mt][nt][2], acc[mt][nt][3]);
        }
    }
}

__global__ void __launch_bounds__(256, 1) kg_proj()
{
    const int z = blockIdx.z;
    const size_t ao = (size_t)blockIdx.y * 128 * 2048;
    const size_t bo = (size_t)blockIdx.x * 128 * 2048;
    if (z == 0)
        gemm_f16_3t(g_xh + ao, g_xl + ao, g_wqh + bo, g_wql + bo,
                    g_q + ao + blockIdx.x * 128, E_);
    else if (z == 1)
        gemm_f16_3t(g_xh + ao, g_xl + ao, g_wkh + bo, g_wkl + bo,
                    g_k + ao + blockIdx.x * 128, E_);
    else
        gemm_f16(g_xh + ao, g_xl + ao, g_wvh + bo,
                 g_v + ao + blockIdx.x * 128, E_);
}

__global__ void __launch_bounds__(256, 1) kg_out(float* out)
{
    const size_t ao = (size_t)blockIdx.y * 128 * 2048;
    const size_t bo = (size_t)blockIdx.x * 128 * 2048;
    gemm_f16(g_aoh + ao, g_aol + ao, g_woh + bo, out + ao + blockIdx.x * 128, HD);
}

// ---------------------------------------------------------------------------
// Flash attention. S-path fp16 3-term (Q hi/lo x K hi/lo), PV fp16 2-term.
// SMEM: QH 32K | QL 32K | 2 st x (KH 16K | KL 16K | V 16K) | PH 16K | PL 16K
// ---------------------------------------------------------------------------
#define FL_SMEM 197632

__global__ void __launch_bounds__(256, 1) k_flash()
{
    extern __shared__ char dsm[];
    const uint32_t s0 = ((uint32_t)__cvta_generic_to_shared(dsm) + 1023) & ~1023u;
    const uint32_t PH = s0 + 163840u, PL = s0 + 180224u;

    const int qt = blockIdx.x, z = blockIdx.y, b = z >> 4, h = z & 15;
    const int tid = threadIdx.x, warp = tid >> 5, lane = tid & 31;
    const int g = lane >> 2, t = lane & 3;

    // ---- Q load (once): hi/lo x 2 planes x 128 rows x 8 chunks
    {
        const __half* qsrc[2] = {g_qnh, g_qnl};
#pragma unroll
        for (int sp = 0; sp < 2; sp++) {
            const uint32_t db = s0 + (uint32_t)sp * 32768u;
#pragma unroll
            for (int j = 0; j < 8; j++) {
                const int i = tid + j * 256;
                const int pl = i >> 10, row = (i >> 3) & 127, ch = i & 7;
                cpa16(db + pl * 16384u + row * 128u + ((ch ^ (row & 7)) << 4),
                      qsrc[sp] + ((size_t)(b * S_ + qt * 128 + row)) * 2048
                               + h * 128 + pl * 64 + ch * 8);
            }
        }
    }

    auto issue_kv = [&](int it) {
        const uint32_t stb = s0 + 65536u + (uint32_t)(it & 1) * 49152u;
        const int kt = it * 64;
        const __half* ksrc[2] = {g_knh, g_knl};
#pragma unroll
        for (int sp = 0; sp < 2; sp++) {
            const uint32_t kb = stb + (uint32_t)sp * 16384u;
#pragma unroll
            for (int j = 0; j < 4; j++) {
                const int i = tid + j * 256;
                const int pl = i >> 9, row = (i >> 3) & 63, ch = i & 7;
                cpa16(kb + pl * 8192u + row * 128u + ((ch ^ (row & 7)) << 4),
                      ksrc[sp] + ((size_t)(b * S_ + kt + row)) * 2048
                               + h * 128 + pl * 64 + ch * 8);
            }
        }
        // V^T single: 128 d-rows x 8 chunks
#pragma unroll
        for (int j = 0; j < 4; j++) {
            const int i = tid + j * 256;
            const int row = i >> 3, ch = i & 7;
            cpa16(stb + 32768u + row * 128u + ((ch ^ (row & 7)) << 4),
                  g_vth + (size_t)z * D_ * S_ + (size_t)row * S_ + kt + ch * 8);
        }
        CP_COMMIT();
    };

    issue_kv(0);

    float oacc[16][4];
#pragma unroll
    for (int i = 0; i < 16; i++)
#pragma unroll
        for (int e = 0; e < 4; e++) oacc[i][e] = 0.0f;
    float mprev0 = -1e30f, mprev1 = -1e30f, lsum0 = 0.0f, lsum1 = 0.0f;

    for (int it = 0; it < 32; it++) {
        if (it + 1 < 32) { issue_kv(it + 1); cp_wait<1>(); }
        else             { cp_wait<0>(); }
        __syncthreads();

        const uint32_t stb = s0 + 65536u + (uint32_t)(it & 1) * 49152u;

        // ---- S = (Qh+Ql)(Kh+Kl)^T 3-term, 16 rows x 64 keys per warp
        float sacc[8][4];
#pragma unroll
        for (int i = 0; i < 8; i++)
#pragma unroll
            for (int e = 0; e < 4; e++) sacc[i][e] = 0.0f;

#pragma unroll
        for (int p = 0; p < 2; p++) {
            const uint32_t qh = s0 + p * 16384u;
            const uint32_t ql = s0 + 32768u + p * 16384u;
            const uint32_t kh = stb + p * 8192u;
            const uint32_t kl = stb + 16384u + p * 8192u;
#pragma unroll
            for (int ks = 0; ks < 4; ks++) {
                const int ra = warp * 16 + (lane & 15);
                const int ca = ks * 2 + (lane >> 4);
                const uint32_t offA = ra * 128u + ((ca ^ (ra & 7)) << 4);
                uint32_t ah[4], al[4];
                LDMX4(ah, qh + offA);
                LDMX4(al, ql + offA);
#pragma unroll
                for (int np = 0; np < 4; np++) {
                    const int rb = np * 16 + (lane & 15);
                    const int cb = ks * 2 + (lane >> 4);
                    const uint32_t offB = rb * 128u + ((cb ^ (rb & 7)) << 4);
                    uint32_t b4h[4], b4l[4];
                    LDMX4(b4h, kh + offB);
                    LDMX4(b4l, kl + offB);
                    uint32_t be[2] = {b4h[0], b4h[2]};
                    uint32_t bo[2] = {b4h[1], b4h[3]};
                    uint32_t le[2] = {b4l[0], b4l[2]};
                    uint32_t lo[2] = {b4l[1], b4l[3]};
                    mma_f16(sacc[2*np],   ah, be);
                    mma_f16(sacc[2*np],   ah, le);
                    mma_f16(sacc[2*np],   al, be);
                    mma_f16(sacc[2*np+1], ah, bo);
                    mma_f16(sacc[2*np+1], ah, lo);
                    mma_f16(sacc[2*np+1], al, bo);
                }
            }
        }

        // ---- online softmax
        float mx0 = -1e30f, mx1 = -1e30f;
#pragma unroll
        for (int i = 0; i < 8; i++) {
            mx0 = fmaxf(mx0, fmaxf(sacc[i][0], sacc[i][1]));
            mx1 = fmaxf(mx1, fmaxf(sacc[i][2], sacc[i][3]));
        }
        mx0 = fmaxf(mx0, __shfl_xor_sync(0xffffffffu, mx0, 1));
        mx0 = fmaxf(mx0, __shfl_xor_sync(0xffffffffu, mx0, 2));
        mx1 = fmaxf(mx1, __shfl_xor_sync(0xffffffffu, mx1, 1));
        mx1 = fmaxf(mx1, __shfl_xor_sync(0xffffffffu, mx1, 2));

        const float mn0 = fmaxf(mprev0, mx0);
        const float mn1 = fmaxf(mprev1, mx1);
        const float sc0 = __expf(mprev0 - mn0);
        const float sc1 = __expf(mprev1 - mn1);
        mprev0 = mn0; mprev1 = mn1;

        float su0 = 0.0f, su1 = 0.0f;
#pragma unroll
        for (int i = 0; i < 8; i++) {
            sacc[i][0] = __expf(sacc[i][0] - mn0);
            sacc[i][1] = __expf(sacc[i][1] - mn0);
            sacc[i][2] = __expf(sacc[i][2] - mn1);
            sacc[i][3] = __expf(sacc[i][3] - mn1);
            su0 += sacc[i][0] + sacc[i][1];
            su1 += sacc[i][2] + sacc[i][3];
        }
        su0 += __shfl_xor_sync(0xffffffffu, su0, 1);
        su0 += __shfl_xor_sync(0xffffffffu, su0, 2);
        su1 += __shfl_xor_sync(0xffffffffu, su1, 1);
        su1 += __shfl_xor_sync(0xffffffffu, su1, 2);
        lsum0 = lsum0 * sc0 + su0;
        lsum1 = lsum1 * sc1 + su1;

#pragma unroll
        for (int i = 0; i < 16; i++) {
            oacc[i][0] *= sc0; oacc[i][1] *= sc0;
            oacc[i][2] *= sc1; oacc[i][3] *= sc1;
        }

        // ---- store P hi/lo to SMEM (A-operand layout)
        const uint32_t smem_gen = (uint32_t)__cvta_generic_to_shared(dsm);
#pragma unroll
        for (int nt = 0; nt < 8; nt++) {
#pragma unroll
            for (int r = 0; r < 2; r++) {
                const float v0 = sacc[nt][2*r], v1 = sacc[nt][2*r+1];
                __half h0, l0, h1, l1;
                split_h(v0, h0, l0); split_h(v1, h1, l1);
                const int row = warp * 16 + g + r * 8;
                const uint32_t off = row * 128u + ((nt ^ (row & 7)) << 4) + t * 4u;
                *(uint32_t*)(dsm + (PH + off - smem_gen)) = pack2h(h0, h1);
                *(uint32_t*)(dsm + (PL + off - smem_gen)) = pack2h(l0, l1);
            }
        }
        __syncwarp();

        // ---- O += (Ph+Pl) V
        const uint32_t vb = stb + 32768u;
#pragma unroll
        for (int ks = 0; ks < 4; ks++) {
            const int ra = warp * 16 + (lane & 15);
            const int ca = ks * 2 + (lane >> 4);
            const uint32_t offA = ra * 128u + ((ca ^ (ra & 7)) << 4);
            uint32_t ph_[4], pl_[4];
            LDMX4(ph_, PH + offA);
            LDMX4(pl_, PL + offA);
#pragma unroll
            for (int np = 0; np < 8; np++) {
                const int rb = np * 16 + (lane & 15);
                const int cb = ks * 2 + (lane >> 4);
                const uint32_t offB = rb * 128u + ((cb ^ (rb & 7)) << 4);
                uint32_t v4[4];
                LDMX4(v4, vb + offB);
                uint32_t be[2] = {v4[0], v4[2]};
                uint32_t bo[2] = {v4[1], v4[3]};
                mma_f16(oacc[2*np],   ph_, be);
                mma_f16(oacc[2*np],   pl_, be);
                mma_f16(oacc[2*np+1], ph_, bo);
                mma_f16(oacc[2*np+1], pl_, bo);
            }
        }
        __syncthreads();
    }

    // ---- epilogue
    const float inv0 = 1.0f / lsum0, inv1 = 1.0f / lsum1;
    const int row0 = b * S_ + qt * 128 + warp * 16 + g;
#pragma unroll
    for (int nt = 0; nt < 16; nt++) {
        const int col = h * 128 + nt * 8 + 2 * t;
        {
            const float o0 = oacc[nt][0] * inv0, o1 = oacc[nt][1] * inv0;
            __half h0, l0, h1, l1;
            split_h(o0, h0, l0); split_h(o1, h1, l1);
            *(uint32_t*)(g_aoh + (size_t)row0 * 2048 + col) = pack2h(h0, h1);
            *(uint32_t*)(g_aol + (size_t)row0 * 2048 + col) = pack2h(l0, l1);
        }
        {
            const float o0 = oacc[nt][2] * inv1, o1 = oacc[nt][3] * inv1;
            __half h0, l0, h1, l1;
            split_h(o0, h0, l0); split_h(o1, h1, l1);
            *(uint32_t*)(g_aoh + (size_t)(row0 + 8) * 2048 + col) = pack2h(h0, h1);
            *(uint32_t*)(g_aol + (size_t)(row0 + 8) * 2048 + col) = pack2h(l0, l1);
        }
    }
}

// ---------------------------------------------------------------------------
// Prep / conversion kernels
// ---------------------------------------------------------------------------
__global__ void k_prep_w(const float* __restrict__ wq, const float* __restrict__ wk,
                         const float* __restrict__ wv, const float* __restrict__ wo)
{
    __shared__ float tbuf[32][33];
    const int z = blockIdx.z;
    const float* src = (z == 0) ? wq : (z == 1) ? wk : (z == 2) ? wv : wo;
    __half* dh = (z == 0) ? g_wqh : (z == 1) ? g_wkh : (z == 2) ? g_wvh : g_woh;
    __half* dl = (z == 0) ? g_wql : (z == 1) ? g_wkl : nullptr;
    const int x0 = blockIdx.x * 32, y0 = blockIdx.y * 32;
    const int tx = threadIdx.x, ty = threadIdx.y;
#pragma unroll
    for (int j = ty; j < 32; j += 8)
        tbuf[j][tx] = src[(size_t)(y0 + j) * 2048 + x0 + tx];
    __syncthreads();
#pragma unroll
    for (int j = ty; j < 32; j += 8) {
        const float v = tbuf[tx][j];
        const size_t idx = (size_t)(x0 + j) * 2048 + y0 + tx;
        if (dl) {
            __half h, l; split_h(v, h, l);
            dh[idx] = h; dl[idx] = l;
        } else {
            dh[idx] = __float2half_rn(v);
        }
    }
}

__global__ void k_prep_x(const float* __restrict__ x)
{
    const size_t i = ((size_t)blockIdx.x * 256 + threadIdx.x) * 4;
    const float4 v = *(const float4*)(x + i);
    __half h[4], l[4];
    split_h(v.x, h[0], l[0]); split_h(v.y, h[1], l[1]);
    split_h(v.z, h[2], l[2]); split_h(v.w, h[3], l[3]);
    *(uint2*)(g_xh + i) = *(uint2*)h;
    *(uint2*)(g_xl + i) = *(uint2*)l;
}

__global__ void __launch_bounds__(256) k_rmsnorm(const float* __restrict__ qs,
                                                 const float* __restrict__ ks)
{
    const int gg   = blockIdx.x * 8 + (threadIdx.x >> 5);
    const int lane = threadIdx.x & 31;
    const float* tp = (blockIdx.y == 0) ? g_q : g_k;
    const float* sc = (blockIdx.y == 0) ? qs : ks;
    __half* oh = (blockIdx.y == 0) ? g_qnh : g_knh;
    __half* ol = (blockIdx.y == 0) ? g_qnl : g_knl;

    float4 v = *((const float4*)(tp + (size_t)gg * 128) + lane);
    float ss = v.x * v.x + v.y * v.y + v.z * v.z + v.w * v.w;
#pragma unroll
    for (int o = 16; o; o >>= 1) ss += __shfl_xor_sync(0xffffffffu, ss, o);
    const float r = rsqrtf(ss * (1.0f / 128.0f) + 1e-6f);
    const float4 s = *((const float4*)sc + lane);
    v.x *= r * s.x; v.y *= r * s.y; v.z *= r * s.z; v.w *= r * s.w;

    __half h[4], l[4];
    split_h(v.x, h[0], l[0]); split_h(v.y, h[1], l[1]);
    split_h(v.z, h[2], l[2]); split_h(v.w, h[3], l[3]);
    const size_t off = (size_t)gg * 128 + lane * 4;
    *(uint2*)(oh + off) = *(uint2*)h;
    *(uint2*)(ol + off) = *(uint2*)l;
}

__global__ void k_vt()
{
    __shared__ float tbuf[32][33];
    const int z = blockIdx.z, b = z >> 4, h = z & 15;
    const int s0 = blockIdx.x * 32, d0 = blockIdx.y * 32;
    const int tx = threadIdx.x, ty = threadIdx.y;
#pragma unroll
    for (int j = ty; j < 32; j += 8)
        tbuf[j][tx] = g_v[((size_t)b * S_ + s0 + j) * 2048 + h * 128 + d0 + tx];
    __syncthreads();
#pragma unroll
    for (int j = ty; j < 32; j += 8)
        g_vth[(size_t)z * D_ * S_ + (size_t)(d0 + j) * S_ + s0 + tx] =
            __float2half_rn(tbuf[tx][j]);
}

// ---------------------------------------------------------------------------
extern "C" void kernel_launch(void* const* d_in, const int* in_sizes, int n_in,
                              void* d_out, int out_size)
{
    const float* x  = (const float*)d_in[0];
    const float* wq = (const float*)d_in[1];
    const float* wk = (const float*)d_in[2];
    const float* wv = (const float*)d_in[3];
    const float* wo = (const float*)d_in[4];
    const float* qs = (const float*)d_in[5];
    const float* ks = (const float*)d_in[6];
    float* out = (float*)d_out;

    constexpr int SMEM3 = 2 * 65536 + 1024;  // 3-term gemm: 132096
    cudaFuncSetAttribute(kg_proj, cudaFuncAttributeMaxDynamicSharedMemorySize, SMEM3);
    cudaFuncSetAttribute(kg_out,  cudaFuncAttributeMaxDynamicSharedMemorySize, SMEM3);
    cudaFuncSetAttribute(k_flash, cudaFuncAttributeMaxDynamicSharedMemorySize, FL_SMEM);

    k_prep_w <<<dim3(64, 64, 4), dim3(32, 8)>>>(wq, wk, wv, wo);
    k_prep_x <<<8192, 256>>>(x);
    kg_proj  <<<dim3(16, 32, 3), 256, SMEM3>>>();
    k_rmsnorm<<<dim3(8192, 2), 256>>>(qs, ks);
    k_vt     <<<dim3(64, 4, 32), dim3(32, 8)>>>();
    k_flash  <<<dim3(16, 32), 256, FL_SMEM>>>();
    kg_out   <<<dim3(16, 32), 256, SMEM3>>>(out);
}

// round 8
// speedup vs baseline: 4.1117x; 1.1389x over previous
#include <cuda_runtime.h>
#include <cuda_fp16.h>
#include <cstdint>

#define B_  2
#define S_  2048
#define E_  2048
#define H_  16
#define D_  128
#define M_  (B_ * S_)     // 4096
#define HD  2048

// ---------------------------------------------------------------------------
// Scratch (device globals — allocation-free per harness rules)
// ---------------------------------------------------------------------------
__device__ float g_v [(size_t)M_ * HD];                              // fp32 V

__device__ __half g_xh [(size_t)M_ * E_],  g_xl [(size_t)M_ * E_];   // x split
__device__ __half g_wqh[(size_t)HD * E_],  g_wql[(size_t)HD * E_];   // wq split [n][k]
__device__ __half g_wkh[(size_t)HD * E_],  g_wkl[(size_t)HD * E_];   // wk split
__device__ __half g_wvh[(size_t)HD * E_];                            // wv single
__device__ __half g_woh[(size_t)E_ * HD];                            // wo single
__device__ __half g_qnh[(size_t)M_ * HD],  g_qnl[(size_t)M_ * HD];   // qn split
__device__ __half g_knh[(size_t)M_ * HD],  g_knl[(size_t)M_ * HD];   // kn split
__device__ __half g_vth[(size_t)B_*H_*D_*S_];                        // V^T single [z][d][s]
__device__ __half g_aoh[(size_t)M_ * HD];                            // ao single

// ---------------------------------------------------------------------------
// helpers
// ---------------------------------------------------------------------------
__device__ __forceinline__ void cpa16(uint32_t dst, const void* src) {
    asm volatile("cp.async.cg.shared.global [%0], [%1], 16;\n" :: "r"(dst), "l"(src));
}
#define CP_COMMIT() asm volatile("cp.async.commit_group;\n" ::: "memory")
template <int N>
__device__ __forceinline__ void cp_wait() {
    asm volatile("cp.async.wait_group %0;\n" :: "n"(N) : "memory");
}
#define LDMX4(r, a) \
    asm volatile("ldmatrix.sync.aligned.m8n8.x4.shared.b16 {%0,%1,%2,%3}, [%4];" \
        : "=r"((r)[0]), "=r"((r)[1]), "=r"((r)[2]), "=r"((r)[3]) : "r"(a))
#define LDMX2(r, a) \
    asm volatile("ldmatrix.sync.aligned.m8n8.x2.shared.b16 {%0,%1}, [%2];" \
        : "=r"((r)[0]), "=r"((r)[1]) : "r"(a))

__device__ __forceinline__ void mma_f16(float* c, const uint32_t* a, const uint32_t* b) {
    asm volatile(
        "mma.sync.aligned.m16n8k16.row.col.f32.f16.f16.f32 "
        "{%0,%1,%2,%3},{%4,%5,%6,%7},{%8,%9},{%0,%1,%2,%3};"
        : "+f"(c[0]), "+f"(c[1]), "+f"(c[2]), "+f"(c[3])
        : "r"(a[0]), "r"(a[1]), "r"(a[2]), "r"(a[3]), "r"(b[0]), "r"(b[1]));
}

__device__ __forceinline__ void split_h(float x, __half& h, __half& l) {
    h = __float2half_rn(x);
    l = __float2half_rn(x - __half2float(h));
}
__device__ __forceinline__ uint32_t pack2h(__half a, __half b) {
    __half2 v; v.x = a; v.y = b;
    return *(uint32_t*)&v;
}

// ---------------------------------------------------------------------------
// fp16 1-term GEMM: C = Ah[128,K] * Bh[128,K]^T -> fp32 C. 32KB/stage x2.
// ---------------------------------------------------------------------------
__device__ __forceinline__ void gemm_f16_1t(const __half* __restrict__ Ah,
                                            const __half* __restrict__ Bh,
                                            float* __restrict__ C, int K)
{
    extern __shared__ char dsm[];
    const uint32_t s0 = ((uint32_t)__cvta_generic_to_shared(dsm) + 1023) & ~1023u;

    const int tid  = threadIdx.x;
    const int warp = tid >> 5;
    const int lane = tid & 31;
    const int g    = lane >> 2;
    const int t    = lane & 3;
    const int m0w  = (warp & 1) * 64;
    const int n0w  = (warp >> 1) * 32;

    const __half* srcs[2] = {Ah, Bh};

    float acc[4][4][4];
#pragma unroll
    for (int i = 0; i < 4; i++)
#pragma unroll
        for (int j = 0; j < 4; j++)
#pragma unroll
            for (int e = 0; e < 4; e++) acc[i][j][e] = 0.0f;

    const int nch = K >> 6;

    auto issue = [&](int c) {
        const uint32_t stb = s0 + (uint32_t)(c & 1) * 32768u;
        const int kt = c * 64;
#pragma unroll
        for (int arr = 0; arr < 2; arr++) {
            const __half* sp = srcs[arr];
            const uint32_t ab = stb + (uint32_t)arr * 16384u;
#pragma unroll
            for (int j = 0; j < 4; j++) {
                const int loc = tid + j * 256;
                const int row = loc >> 3;
                const int ch  = loc & 7;
                const uint32_t off = (uint32_t)row * 128u
                                   + (uint32_t)((ch ^ (row & 7)) << 4);
                cpa16(ab + off, sp + (size_t)row * 2048 + kt + ch * 8);
            }
        }
        CP_COMMIT();
    };

    issue(0);

    for (int c = 0; c < nch; c++) {
        if (c + 1 < nch) { issue(c + 1); cp_wait<1>(); }
        else             { cp_wait<0>(); }
        __syncthreads();

        const uint32_t stb = s0 + (uint32_t)(c & 1) * 32768u;
        const uint32_t aB  = stb;
        const uint32_t bB  = stb + 16384u;

#pragma unroll
        for (int ks = 0; ks < 4; ks++) {
            uint32_t bh[4][2];
#pragma unroll
            for (int nt = 0; nt < 4; nt++) {
                const int rb = n0w + nt * 8 + (lane & 7);
                const int cb = ks * 2 + ((lane >> 3) & 1);
                const uint32_t off = (uint32_t)rb * 128u
                                   + (uint32_t)((cb ^ (rb & 7)) << 4);
                LDMX2(bh[nt], bB + off);
            }
#pragma unroll
            for (int mt = 0; mt < 4; mt++) {
                const int ra = m0w + mt * 16 + (lane & 15);
                const int ca = ks * 2 + (lane >> 4);
                const uint32_t off = (uint32_t)ra * 128u
                                   + (uint32_t)((ca ^ (ra & 7)) << 4);
                uint32_t ah[4];
                LDMX4(ah, aB + off);
#pragma unroll
                for (int nt = 0; nt < 4; nt++)
                    mma_f16(acc[mt][nt], ah, bh[nt]);
            }
        }
        __syncthreads();
    }

#pragma unroll
    for (int mt = 0; mt < 4; mt++) {
#pragma unroll
        for (int nt = 0; nt < 4; nt++) {
            const int r0 = m0w + mt * 16 + g;
            const int c0 = n0w + nt * 8 + 2 * t;
            *(float2*)(C + (size_t)r0 * 2048 + c0) =
                make_float2(acc[mt][nt][0], acc[mt][nt][1]);
            *(float2*)(C + (size_t)(r0 + 8) * 2048 + c0) =
                make_float2(acc[mt][nt][2], acc[mt][nt][3]);
        }
    }
}

// ---------------------------------------------------------------------------
// fp16 3-term GEMM with fused RMS-norm epilogue -> fp16 hi/lo outputs.
// Output tile = 128 tokens x one head's D=128. 64KB/stage x2.
// ---------------------------------------------------------------------------
__device__ __forceinline__ void gemm_qk_3t(const __half* __restrict__ Ah,
                                           const __half* __restrict__ Al,
                                           const __half* __restrict__ Bh,
                                           const __half* __restrict__ Bl,
                                           const float* __restrict__ sc,
                                           __half* __restrict__ Oh,
                                           __half* __restrict__ Ol,
                                           size_t obase, int K)
{
    extern __shared__ char dsm[];
    const uint32_t smem_gen = (uint32_t)__cvta_generic_to_shared(dsm);
    const uint32_t s0 = (smem_gen + 1023) & ~1023u;

    const int tid  = threadIdx.x;
    const int warp = tid >> 5;
    const int lane = tid & 31;
    const int g    = lane >> 2;
    const int t    = lane & 3;
    const int m0w  = (warp & 1) * 64;
    const int n0w  = (warp >> 1) * 32;

    const __half* srcs[4] = {Ah, Al, Bh, Bl};

    float acc[4][4][4];
#pragma unroll
    for (int i = 0; i < 4; i++)
#pragma unroll
        for (int j = 0; j < 4; j++)
#pragma unroll
            for (int e = 0; e < 4; e++) acc[i][j][e] = 0.0f;

    const int nch = K >> 6;

    auto issue = [&](int c) {
        const uint32_t stb = s0 + (uint32_t)(c & 1) * 65536u;
        const int kt = c * 64;
#pragma unroll
        for (int arr = 0; arr < 4; arr++) {
            const __half* sp = srcs[arr];
            const uint32_t ab = stb + (uint32_t)arr * 16384u;
#pragma unroll
            for (int j = 0; j < 4; j++) {
                const int loc = tid + j * 256;
                const int row = loc >> 3;
                const int ch  = loc & 7;
                const uint32_t off = (uint32_t)row * 128u
                                   + (uint32_t)((ch ^ (row & 7)) << 4);
                cpa16(ab + off, sp + (size_t)row * 2048 + kt + ch * 8);
            }
        }
        CP_COMMIT();
    };

    issue(0);

    for (int c = 0; c < nch; c++) {
        if (c + 1 < nch) { issue(c + 1); cp_wait<1>(); }
        else             { cp_wait<0>(); }
        __syncthreads();

        const uint32_t stb = s0 + (uint32_t)(c & 1) * 65536u;
        const uint32_t aB  = stb;
        const uint32_t bB  = stb + 32768u;

#pragma unroll
        for (int ks = 0; ks < 4; ks++) {
            uint32_t bh[4][2], bl[4][2];
#pragma unroll
            for (int nt = 0; nt < 4; nt++) {
                const int rb = n0w + nt * 8 + (lane & 7);
                const int cb = ks * 2 + ((lane >> 3) & 1);
                const uint32_t off = (uint32_t)rb * 128u
                                   + (uint32_t)((cb ^ (rb & 7)) << 4);
                LDMX2(bh[nt], bB + off);
                LDMX2(bl[nt], bB + 16384u + off);
            }
#pragma unroll
            for (int mt = 0; mt < 4; mt++) {
                const int ra = m0w + mt * 16 + (lane & 15);
                const int ca = ks * 2 + (lane >> 4);
                const uint32_t off = (uint32_t)ra * 128u
                                   + (uint32_t)((ca ^ (ra & 7)) << 4);
                uint32_t ah[4], al[4];
                LDMX4(ah, aB + off);
                LDMX4(al, aB + 16384u + off);
#pragma unroll
                for (int nt = 0; nt < 4; nt++) {
                    mma_f16(acc[mt][nt], ah, bh[nt]);
                    mma_f16(acc[mt][nt], ah, bl[nt]);
                    mma_f16(acc[mt][nt], al, bh[nt]);
                }
            }
        }
        __syncthreads();
    }

    // ---- fused RMS-norm epilogue ----
    // partial sums of squares per row: [n-group 0..3][row 0..127]
    float* part = (float*)(dsm + (s0 - smem_gen));
    const int ng = warp >> 1;
#pragma unroll
    for (int mt = 0; mt < 4; mt++) {
#pragma unroll
        for (int r = 0; r < 2; r++) {
            float p = 0.0f;
#pragma unroll
            for (int nt = 0; nt < 4; nt++) {
                const float a0 = acc[mt][nt][2*r], a1 = acc[mt][nt][2*r+1];
                p += a0 * a0 + a1 * a1;
            }
            p += __shfl_xor_sync(0xffffffffu, p, 1);
            p += __shfl_xor_sync(0xffffffffu, p, 2);
            if (t == 0)
                part[ng * 128 + m0w + mt * 16 + g + r * 8] = p;
        }
    }
    __syncthreads();

#pragma unroll
    for (int mt = 0; mt < 4; mt++) {
#pragma unroll
        for (int r = 0; r < 2; r++) {
            const int row = m0w + mt * 16 + g + r * 8;
            const float sum = part[row] + part[128 + row]
                            + part[256 + row] + part[384 + row];
            const float rs = rsqrtf(sum * (1.0f / 128.0f) + 1e-6f);
#pragma unroll
            for (int nt = 0; nt < 4; nt++) {
                const int col = n0w + nt * 8 + 2 * t;
                const float2 sv = *(const float2*)(sc + col);
                const float v0 = acc[mt][nt][2*r]   * rs * sv.x;
                const float v1 = acc[mt][nt][2*r+1] * rs * sv.y;
                __half h0, l0, h1, l1;
                split_h(v0, h0, l0); split_h(v1, h1, l1);
                const size_t idx = obase + (size_t)row * 2048 + col;
                *(uint32_t*)(Oh + idx) = pack2h(h0, h1);
                *(uint32_t*)(Ol + idx) = pack2h(l0, l1);
            }
        }
    }
}

__global__ void __launch_bounds__(256, 1) kg_proj(const float* __restrict__ qs,
                                                  const float* __restrict__ ks)
{
    const int z = blockIdx.z;
    const size_t ao = (size_t)blockIdx.y * 128 * 2048;
    const size_t bo = (size_t)blockIdx.x * 128 * 2048;
    const size_t ob = ao + blockIdx.x * 128;
    if (z == 0)
        gemm_qk_3t(g_xh + ao, g_xl + ao, g_wqh + bo, g_wql + bo,
                   qs, g_qnh, g_qnl, ob, E_);
    else if (z == 1)
        gemm_qk_3t(g_xh + ao, g_xl + ao, g_wkh + bo, g_wkl + bo,
                   ks, g_knh, g_knl, ob, E_);
    else
        gemm_f16_1t(g_xh + ao, g_wvh + bo, g_v + ob, E_);
}

__global__ void __launch_bounds__(256, 1) kg_out(float* out)
{
    const size_t ao = (size_t)blockIdx.y * 128 * 2048;
    const size_t bo = (size_t)blockIdx.x * 128 * 2048;
    gemm_f16_1t(g_aoh + ao, g_woh + bo, out + ao + blockIdx.x * 128, HD);
}

// ---------------------------------------------------------------------------
// Flash attention. S-path fp16 3-term, PV fp16 2-term, output single fp16.
// SMEM: QH 32K | QL 32K | 2 st x (KH 16K | KL 16K | V 16K) | PH 16K | PL 16K
// ---------------------------------------------------------------------------
#define FL_SMEM 197632

__global__ void __launch_bounds__(256, 1) k_flash()
{
    extern __shared__ char dsm[];
    const uint32_t s0 = ((uint32_t)__cvta_generic_to_shared(dsm) + 1023) & ~1023u;
    const uint32_t PH = s0 + 163840u, PL = s0 + 180224u;

    const int qt = blockIdx.x, z = blockIdx.y, b = z >> 4, h = z & 15;
    const int tid = threadIdx.x, warp = tid >> 5, lane = tid & 31;
    const int g = lane >> 2, t = lane & 3;

    // ---- Q load (once)
    {
        const __half* qsrc[2] = {g_qnh, g_qnl};
#pragma unroll
        for (int sp = 0; sp < 2; sp++) {
            const uint32_t db = s0 + (uint32_t)sp * 32768u;
#pragma unroll
            for (int j = 0; j < 8; j++) {
                const int i = tid + j * 256;
                const int pl = i >> 10, row = (i >> 3) & 127, ch = i & 7;
                cpa16(db + pl * 16384u + row * 128u + ((ch ^ (row & 7)) << 4),
                      qsrc[sp] + ((size_t)(b * S_ + qt * 128 + row)) * 2048
                               + h * 128 + pl * 64 + ch * 8);
            }
        }
    }

    auto issue_kv = [&](int it) {
        const uint32_t stb = s0 + 65536u + (uint32_t)(it & 1) * 49152u;
        const int kt = it * 64;
        const __half* ksrc[2] = {g_knh, g_knl};
#pragma unroll
        for (int sp = 0; sp < 2; sp++) {
            const uint32_t kb = stb + (uint32_t)sp * 16384u;
#pragma unroll
            for (int j = 0; j < 4; j++) {
                const int i = tid + j * 256;
                const int pl = i >> 9, row = (i >> 3) & 63, ch = i & 7;
                cpa16(kb + pl * 8192u + row * 128u + ((ch ^ (row & 7)) << 4),
                      ksrc[sp] + ((size_t)(b * S_ + kt + row)) * 2048
                               + h * 128 + pl * 64 + ch * 8);
            }
        }
#pragma unroll
        for (int j = 0; j < 4; j++) {
            const int i = tid + j * 256;
            const int row = i >> 3, ch = i & 7;
            cpa16(stb + 32768u + row * 128u + ((ch ^ (row & 7)) << 4),
                  g_vth + (size_t)z * D_ * S_ + (size_t)row * S_ + kt + ch * 8);
        }
        CP_COMMIT();
    };

    issue_kv(0);

    float oacc[16][4];
#pragma unroll
    for (int i = 0; i < 16; i++)
#pragma unroll
        for (int e = 0; e < 4; e++) oacc[i][e] = 0.0f;
    float mprev0 = -1e30f, mprev1 = -1e30f, lsum0 = 0.0f, lsum1 = 0.0f;

    for (int it = 0; it < 32; it++) {
        if (it + 1 < 32) { issue_kv(it + 1); cp_wait<1>(); }
        else             { cp_wait<0>(); }
        __syncthreads();

        const uint32_t stb = s0 + 65536u + (uint32_t)(it & 1) * 49152u;

        float sacc[8][4];
#pragma unroll
        for (int i = 0; i < 8; i++)
#pragma unroll
            for (int e = 0; e < 4; e++) sacc[i][e] = 0.0f;

#pragma unroll
        for (int p = 0; p < 2; p++) {
            const uint32_t qh = s0 + p * 16384u;
            const uint32_t ql = s0 + 32768u + p * 16384u;
            const uint32_t kh = stb + p * 8192u;
            const uint32_t kl = stb + 16384u + p * 8192u;
#pragma unroll
            for (int ks = 0; ks < 4; ks++) {
                const int ra = warp * 16 + (lane & 15);
                const int ca = ks * 2 + (lane >> 4);
                const uint32_t offA = ra * 128u + ((ca ^ (ra & 7)) << 4);
                uint32_t ah[4], al[4];
                LDMX4(ah, qh + offA);
                LDMX4(al, ql + offA);
#pragma unroll
                for (int np = 0; np < 4; np++) {
                    const int rb = np * 16 + (lane & 15);
                    const int cb = ks * 2 + (lane >> 4);
                    const uint32_t offB = rb * 128u + ((cb ^ (rb & 7)) << 4);
                    uint32_t b4h[4], b4l[4];
                    LDMX4(b4h, kh + offB);
                    LDMX4(b4l, kl + offB);
                    uint32_t be[2] = {b4h[0], b4h[2]};
                    uint32_t bo[2] = {b4h[1], b4h[3]};
                    uint32_t le[2] = {b4l[0], b4l[2]};
                    uint32_t lo[2] = {b4l[1], b4l[3]};
                    mma_f16(sacc[2*np],   ah, be);
                    mma_f16(sacc[2*np],   ah, le);
                    mma_f16(sacc[2*np],   al, be);
                    mma_f16(sacc[2*np+1], ah, bo);
                    mma_f16(sacc[2*np+1], ah, lo);
                    mma_f16(sacc[2*np+1], al, bo);
                }
            }
        }

        // ---- online softmax
        float mx0 = -1e30f, mx1 = -1e30f;
#pragma unroll
        for (int i = 0; i < 8; i++) {
            mx0 = fmaxf(mx0, fmaxf(sacc[i][0], sacc[i][1]));
            mx1 = fmaxf(mx1, fmaxf(sacc[i][2], sacc[i][3]));
        }
        mx0 = fmaxf(mx0, __shfl_xor_sync(0xffffffffu, mx0, 1));
        mx0 = fmaxf(mx0, __shfl_xor_sync(0xffffffffu, mx0, 2));
        mx1 = fmaxf(mx1, __shfl_xor_sync(0xffffffffu, mx1, 1));
        mx1 = fmaxf(mx1, __shfl_xor_sync(0xffffffffu, mx1, 2));

        const float mn0 = fmaxf(mprev0, mx0);
        const float mn1 = fmaxf(mprev1, mx1);
        const float sc0 = __expf(mprev0 - mn0);
        const float sc1 = __expf(mprev1 - mn1);
        mprev0 = mn0; mprev1 = mn1;

        float su0 = 0.0f, su1 = 0.0f;
#pragma unroll
        for (int i = 0; i < 8; i++) {
            sacc[i][0] = __expf(sacc[i][0] - mn0);
            sacc[i][1] = __expf(sacc[i][1] - mn0);
            sacc[i][2] = __expf(sacc[i][2] - mn1);
            sacc[i][3] = __expf(sacc[i][3] - mn1);
            su0 += sacc[i][0] + sacc[i][1];
            su1 += sacc[i][2] + sacc[i][3];
        }
        su0 += __shfl_xor_sync(0xffffffffu, su0, 1);
        su0 += __shfl_xor_sync(0xffffffffu, su0, 2);
        su1 += __shfl_xor_sync(0xffffffffu, su1, 1);
        su1 += __shfl_xor_sync(0xffffffffu, su1, 2);
        lsum0 = lsum0 * sc0 + su0;
        lsum1 = lsum1 * sc1 + su1;

#pragma unroll
        for (int i = 0; i < 16; i++) {
            oacc[i][0] *= sc0; oacc[i][1] *= sc0;
            oacc[i][2] *= sc1; oacc[i][3] *= sc1;
        }

        // ---- store P hi/lo to SMEM (A-operand layout)
        const uint32_t smem_gen = (uint32_t)__cvta_generic_to_shared(dsm);
#pragma unroll
        for (int nt = 0; nt < 8; nt++) {
#pragma unroll
            for (int r = 0; r < 2; r++) {
                const float v0 = sacc[nt][2*r], v1 = sacc[nt][2*r+1];
                __half h0, l0, h1, l1;
                split_h(v0, h0, l0); split_h(v1, h1, l1);
                const int row = warp * 16 + g + r * 8;
                const uint32_t off = row * 128u + ((nt ^ (row & 7)) << 4) + t * 4u;
                *(uint32_t*)(dsm + (PH + off - smem_gen)) = pack2h(h0, h1);
                *(uint32_t*)(dsm + (PL + off - smem_gen)) = pack2h(l0, l1);
            }
        }
        __syncwarp();

        // ---- O += (Ph+Pl) V
        const uint32_t vb = stb + 32768u;
#pragma unroll
        for (int ks = 0; ks < 4; ks++) {
            const int ra = warp * 16 + (lane & 15);
            const int ca = ks * 2 + (lane >> 4);
            const uint32_t offA = ra * 128u + ((ca ^ (ra & 7)) << 4);
            uint32_t ph_[4], pl_[4];
            LDMX4(ph_, PH + offA);
            LDMX4(pl_, PL + offA);
#pragma unroll
            for (int np = 0; np < 8; np++) {
                const int rb = np * 16 + (lane & 15);
                const int cb = ks * 2 + (lane >> 4);
                const uint32_t offB = rb * 128u + ((cb ^ (rb & 7)) << 4);
                uint32_t v4[4];
                LDMX4(v4, vb + offB);
                uint32_t be[2] = {v4[0], v4[2]};
                uint32_t bo[2] = {v4[1], v4[3]};
                mma_f16(oacc[2*np],   ph_, be);
                mma_f16(oacc[2*np],   pl_, be);
                mma_f16(oacc[2*np+1], ph_, bo);
                mma_f16(oacc[2*np+1], pl_, bo);
            }
        }
        __syncthreads();
    }

    // ---- epilogue: O / l -> single fp16
    const float inv0 = 1.0f / lsum0, inv1 = 1.0f / lsum1;
    const int row0 = b * S_ + qt * 128 + warp * 16 + g;
#pragma unroll
    for (int nt = 0; nt < 16; nt++) {
        const int col = h * 128 + nt * 8 + 2 * t;
        *(uint32_t*)(g_aoh + (size_t)row0 * 2048 + col) =
            pack2h(__float2half_rn(oacc[nt][0] * inv0),
                   __float2half_rn(oacc[nt][1] * inv0));
        *(uint32_t*)(g_aoh + (size_t)(row0 + 8) * 2048 + col) =
            pack2h(__float2half_rn(oacc[nt][2] * inv1),
                   __float2half_rn(oacc[nt][3] * inv1));
    }
}

// ---------------------------------------------------------------------------
// Prep / conversion kernels
// ---------------------------------------------------------------------------
__global__ void k_prep_w(const float* __restrict__ wq, const float* __restrict__ wk,
                         const float* __restrict__ wv, const float* __restrict__ wo)
{
    __shared__ float tbuf[32][33];
    const int z = blockIdx.z;
    const float* src = (z == 0) ? wq : (z == 1) ? wk : (z == 2) ? wv : wo;
    __half* dh = (z == 0) ? g_wqh : (z == 1) ? g_wkh : (z == 2) ? g_wvh : g_woh;
    __half* dl = (z == 0) ? g_wql : (z == 1) ? g_wkl : nullptr;
    const int x0 = blockIdx.x * 32, y0 = blockIdx.y * 32;
    const int tx = threadIdx.x, ty = threadIdx.y;
#pragma unroll
    for (int j = ty; j < 32; j += 8)
        tbuf[j][tx] = src[(size_t)(y0 + j) * 2048 + x0 + tx];
    __syncthreads();
#pragma unroll
    for (int j = ty; j < 32; j += 8) {
        const float v = tbuf[tx][j];
        const size_t idx = (size_t)(x0 + j) * 2048 + y0 + tx;
        if (dl) {
            __half h, l; split_h(v, h, l);
            dh[idx] = h; dl[idx] = l;
        } else {
            dh[idx] = __float2half_rn(v);
        }
    }
}

__global__ void k_prep_x(const float* __restrict__ x)
{
    const size_t i = ((size_t)blockIdx.x * 256 + threadIdx.x) * 4;
    const float4 v = *(const float4*)(x + i);
    __half h[4], l[4];
    split_h(v.x, h[0], l[0]); split_h(v.y, h[1], l[1]);
    split_h(v.z, h[2], l[2]); split_h(v.w, h[3], l[3]);
    *(uint2*)(g_xh + i) = *(uint2*)h;
    *(uint2*)(g_xl + i) = *(uint2*)l;
}

__global__ void k_vt()
{
    __shared__ float tbuf[32][33];
    const int z = blockIdx.z, b = z >> 4, h = z & 15;
    const int s0 = blockIdx.x * 32, d0 = blockIdx.y * 32;
    const int tx = threadIdx.x, ty = threadIdx.y;
#pragma unroll
    for (int j = ty; j < 32; j += 8)
        tbuf[j][tx] = g_v[((size_t)b * S_ + s0 + j) * 2048 + h * 128 + d0 + tx];
    __syncthreads();
#pragma unroll
    for (int j = ty; j < 32; j += 8)
        g_vth[(size_t)z * D_ * S_ + (size_t)(d0 + j) * S_ + s0 + tx] =
            __float2half_rn(tbuf[tx][j]);
}

// ---------------------------------------------------------------------------
extern "C" void kernel_launch(void* const* d_in, const int* in_sizes, int n_in,
                              void* d_out, int out_size)
{
    const float* x  = (const float*)d_in[0];
    const float* wq = (const float*)d_in[1];
    const float* wk = (const float*)d_in[2];
    const float* wv = (const float*)d_in[3];
    const float* wo = (const float*)d_in[4];
    const float* qs = (const float*)d_in[5];
    const float* ks = (const float*)d_in[6];
    float* out = (float*)d_out;

    constexpr int SMEM3 = 2 * 65536 + 1024;  // 3-term gemm: 132096
    constexpr int SMEM1 = 2 * 32768 + 1024;  // 1-term gemm: 66560
    cudaFuncSetAttribute(kg_proj, cudaFuncAttributeMaxDynamicSharedMemorySize, SMEM3);
    cudaFuncSetAttribute(kg_out,  cudaFuncAttributeMaxDynamicSharedMemorySize, SMEM1);
    cudaFuncSetAttribute(k_flash, cudaFuncAttributeMaxDynamicSharedMemorySize, FL_SMEM);

    k_prep_w <<<dim3(64, 64, 4), dim3(32, 8)>>>(wq, wk, wv, wo);
    k_prep_x <<<8192, 256>>>(x);
    kg_proj  <<<dim3(16, 32, 3), 256, SMEM3>>>(qs, ks);
    k_vt     <<<dim3(64, 4, 32), dim3(32, 8)>>>();
    k_flash  <<<dim3(16, 32), 256, FL_SMEM>>>();
    kg_out   <<<dim3(16, 32), 256, SMEM1>>>(out);
}

// round 9
// speedup vs baseline: 4.2685x; 1.0381x over previous
#include <cuda_runtime.h>
#include <cuda_fp16.h>
#include <cstdint>

#define B_  2
#define S_  2048
#define E_  2048
#define H_  16
#define D_  128
#define M_  (B_ * S_)     // 4096
#define HD  2048

// ---------------------------------------------------------------------------
// Scratch (device globals — allocation-free per harness rules)
// ---------------------------------------------------------------------------
__device__ __half g_xh [(size_t)M_ * E_],  g_xl [(size_t)M_ * E_];   // x split
__device__ __half g_wqh[(size_t)HD * E_],  g_wql[(size_t)HD * E_];   // wq split [n][k]
__device__ __half g_wkh[(size_t)HD * E_],  g_wkl[(size_t)HD * E_];   // wk split
__device__ __half g_wvh[(size_t)HD * E_];                            // wv single
__device__ __half g_woh[(size_t)E_ * HD];                            // wo single
__device__ __half g_qnh[(size_t)M_ * HD],  g_qnl[(size_t)M_ * HD];   // qn split
__device__ __half g_knh[(size_t)M_ * HD],  g_knl[(size_t)M_ * HD];   // kn split
__device__ __half g_vth[(size_t)B_*H_*D_*S_];                        // V^T [z][d][s]
__device__ __half g_aoh[(size_t)M_ * HD];                            // ao single

// ---------------------------------------------------------------------------
// helpers
// ---------------------------------------------------------------------------
__device__ __forceinline__ void cpa16(uint32_t dst, const void* src) {
    asm volatile("cp.async.cg.shared.global [%0], [%1], 16;\n" :: "r"(dst), "l"(src));
}
#define CP_COMMIT() asm volatile("cp.async.commit_group;\n" ::: "memory")
template <int N>
__device__ __forceinline__ void cp_wait() {
    asm volatile("cp.async.wait_group %0;\n" :: "n"(N) : "memory");
}
#define LDMX4(r, a) \
    asm volatile("ldmatrix.sync.aligned.m8n8.x4.shared.b16 {%0,%1,%2,%3}, [%4];" \
        : "=r"((r)[0]), "=r"((r)[1]), "=r"((r)[2]), "=r"((r)[3]) : "r"(a))
#define LDMX2(r, a) \
    asm volatile("ldmatrix.sync.aligned.m8n8.x2.shared.b16 {%0,%1}, [%2];" \
        : "=r"((r)[0]), "=r"((r)[1]) : "r"(a))

__device__ __forceinline__ void mma_f16(float* c, const uint32_t* a, const uint32_t* b) {
    asm volatile(
        "mma.sync.aligned.m16n8k16.row.col.f32.f16.f16.f32 "
        "{%0,%1,%2,%3},{%4,%5,%6,%7},{%8,%9},{%0,%1,%2,%3};"
        : "+f"(c[0]), "+f"(c[1]), "+f"(c[2]), "+f"(c[3])
        : "r"(a[0]), "r"(a[1]), "r"(a[2]), "r"(a[3]), "r"(b[0]), "r"(b[1]));
}

__device__ __forceinline__ void split_h(float x, __half& h, __half& l) {
    h = __float2half_rn(x);
    l = __float2half_rn(x - __half2float(h));
}
__device__ __forceinline__ uint32_t pack2h(__half a, __half b) {
    __half2 v; v.x = a; v.y = b;
    return *(uint32_t*)&v;
}
// 64B-row swizzle: conflict-free ldmatrix groups (r&1)*4 + (ch^((r>>1)&3))
__device__ __forceinline__ uint32_t sw64(int row, int ch) {
    return (uint32_t)row * 64u + (uint32_t)((ch ^ ((row >> 1) & 3)) << 4);
}
// 128B-row swizzle (BK=64 tiles)
__device__ __forceinline__ uint32_t sw128(int row, int ch) {
    return (uint32_t)row * 128u + (uint32_t)((ch ^ (row & 7)) << 4);
}

// ---------------------------------------------------------------------------
// fp16 1-term GEMM core, BK=64, 2-stage. VT=false: fp32 C (ldc 2048).
// VT=true: transposed fp16 epilogue -> dstv[d][s] (V^T layout), C unused.
// ---------------------------------------------------------------------------
template <bool VT>
__device__ __forceinline__ void gemm_f16_1t(const __half* __restrict__ Ah,
                                            const __half* __restrict__ Bh,
                                            float* __restrict__ C,
                                            __half* __restrict__ dstv,
                                            int s0g, int K)
{
    extern __shared__ char dsm[];
    const uint32_t smem_gen = (uint32_t)__cvta_generic_to_shared(dsm);
    const uint32_t s0 = (smem_gen + 1023) & ~1023u;

    const int tid  = threadIdx.x;
    const int warp = tid >> 5;
    const int lane = tid & 31;
    const int g    = lane >> 2;
    const int t    = lane & 3;
    const int m0w  = (warp & 1) * 64;
    const int n0w  = (warp >> 1) * 32;

    const __half* srcs[2] = {Ah, Bh};

    float acc[4][4][4];
#pragma unroll
    for (int i = 0; i < 4; i++)
#pragma unroll
        for (int j = 0; j < 4; j++)
#pragma unroll
            for (int e = 0; e < 4; e++) acc[i][j][e] = 0.0f;

    const int nch = K >> 6;

    auto issue = [&](int c) {
        const uint32_t stb = s0 + (uint32_t)(c & 1) * 32768u;
        const int kt = c * 64;
#pragma unroll
        for (int arr = 0; arr < 2; arr++) {
            const __half* sp = srcs[arr];
            const uint32_t ab = stb + (uint32_t)arr * 16384u;
#pragma unroll
            for (int j = 0; j < 4; j++) {
                const int loc = tid + j * 256;
                const int row = loc >> 3;
                const int ch  = loc & 7;
                cpa16(ab + sw128(row, ch), sp + (size_t)row * 2048 + kt + ch * 8);
            }
        }
        CP_COMMIT();
    };

    issue(0);

    for (int c = 0; c < nch; c++) {
        if (c + 1 < nch) { issue(c + 1); cp_wait<1>(); }
        else             { cp_wait<0>(); }
        __syncthreads();

        const uint32_t stb = s0 + (uint32_t)(c & 1) * 32768u;
        const uint32_t aB  = stb;
        const uint32_t bB  = stb + 16384u;

#pragma unroll
        for (int ks = 0; ks < 4; ks++) {
            uint32_t bh[4][2];
#pragma unroll
            for (int nt = 0; nt < 4; nt++) {
                const int rb = n0w + nt * 8 + (lane & 7);
                const int cb = ks * 2 + ((lane >> 3) & 1);
                LDMX2(bh[nt], bB + sw128(rb, cb));
            }
#pragma unroll
            for (int mt = 0; mt < 4; mt++) {
                const int ra = m0w + mt * 16 + (lane & 15);
                const int ca = ks * 2 + (lane >> 4);
                uint32_t ah[4];
                LDMX4(ah, aB + sw128(ra, ca));
#pragma unroll
                for (int nt = 0; nt < 4; nt++)
                    mma_f16(acc[mt][nt], ah, bh[nt]);
            }
        }
        __syncthreads();
    }

    if (!VT) {
#pragma unroll
        for (int mt = 0; mt < 4; mt++) {
#pragma unroll
            for (int nt = 0; nt < 4; nt++) {
                const int r0 = m0w + mt * 16 + g;
                const int c0 = n0w + nt * 8 + 2 * t;
                *(float2*)(C + (size_t)r0 * 2048 + c0) =
                    make_float2(acc[mt][nt][0], acc[mt][nt][1]);
                *(float2*)(C + (size_t)(r0 + 8) * 2048 + c0) =
                    make_float2(acc[mt][nt][2], acc[mt][nt][3]);
            }
        }
    } else {
        // transpose via SMEM: vt[col][row] fp16, rows padded to 136
        __half* vt = (__half*)(dsm + (s0 - smem_gen));
#pragma unroll
        for (int mt = 0; mt < 4; mt++) {
#pragma unroll
            for (int nt = 0; nt < 4; nt++) {
                const int r0 = m0w + mt * 16 + g;
                const int c0 = n0w + nt * 8 + 2 * t;
                vt[(c0    ) * 136 + r0    ] = __float2half_rn(acc[mt][nt][0]);
                vt[(c0 + 1) * 136 + r0    ] = __float2half_rn(acc[mt][nt][1]);
                vt[(c0    ) * 136 + r0 + 8] = __float2half_rn(acc[mt][nt][2]);
                vt[(c0 + 1) * 136 + r0 + 8] = __float2half_rn(acc[mt][nt][3]);
            }
        }
        __syncthreads();
#pragma unroll
        for (int j = 0; j < 8; j++) {
            const int vec = tid + j * 256;      // 0..2047
            const int d  = vec >> 4;            // 0..127
            const int sc = vec & 15;            // 0..15 (8 tokens each)
            uint4 v;
            v.x = *(uint32_t*)&vt[d * 136 + sc * 8 + 0];
            v.y = *(uint32_t*)&vt[d * 136 + sc * 8 + 2];
            v.z = *(uint32_t*)&vt[d * 136 + sc * 8 + 4];
            v.w = *(uint32_t*)&vt[d * 136 + sc * 8 + 6];
            *(uint4*)(dstv + (size_t)d * S_ + s0g + sc * 8) = v;
        }
    }
}

// ---------------------------------------------------------------------------
// fp16 3-term GEMM, BK=32, 2-stage, 64KB smem -> 2 CTAs/SM.
// Fused RMS-norm epilogue -> fp16 hi/lo outputs.
// ---------------------------------------------------------------------------
__device__ __forceinline__ void gemm_qk_3t(const __half* __restrict__ Ah,
                                           const __half* __restrict__ Al,
                                           const __half* __restrict__ Bh,
                                           const __half* __restrict__ Bl,
                                           const float* __restrict__ sc,
                                           __half* __restrict__ Oh,
                                           __half* __restrict__ Ol,
                                           size_t obase, int K)
{
    extern __shared__ char dsm[];
    const uint32_t smem_gen = (uint32_t)__cvta_generic_to_shared(dsm);
    const uint32_t s0 = (smem_gen + 1023) & ~1023u;

    const int tid  = threadIdx.x;
    const int warp = tid >> 5;
    const int lane = tid & 31;
    const int g    = lane >> 2;
    const int t    = lane & 3;
    const int m0w  = (warp & 1) * 64;
    const int n0w  = (warp >> 1) * 32;

    const __half* srcs[4] = {Ah, Al, Bh, Bl};

    float acc[4][4][4];
#pragma unroll
    for (int i = 0; i < 4; i++)
#pragma unroll
        for (int j = 0; j < 4; j++)
#pragma unroll
            for (int e = 0; e < 4; e++) acc[i][j][e] = 0.0f;

    const int nch = K >> 5;      // BK=32

    auto issue = [&](int c) {
        const uint32_t stb = s0 + (uint32_t)(c & 1) * 32768u;
        const int kt = c * 32;
#pragma unroll
        for (int j = 0; j < 8; j++) {
            const int loc = tid + j * 256;      // 0..2047
            const int arr = loc >> 9;           // 0..3
            const int l2  = loc & 511;
            const int row = l2 >> 2;            // 0..127
            const int ch  = l2 & 3;             // 0..3 (16B chunks of 64B row)
            cpa16(stb + (uint32_t)arr * 8192u + sw64(row, ch),
                  srcs[arr] + (size_t)row * 2048 + kt + ch * 8);
        }
        CP_COMMIT();
    };

    issue(0);

    for (int c = 0; c < nch; c++) {
        if (c + 1 < nch) { issue(c + 1); cp_wait<1>(); }
        else             { cp_wait<0>(); }
        __syncthreads();

        const uint32_t stb = s0 + (uint32_t)(c & 1) * 32768u;
        const uint32_t aH = stb, aL = stb + 8192u;
        const uint32_t bH = stb + 16384u, bL = stb + 24576u;

#pragma unroll
        for (int ks = 0; ks < 2; ks++) {
            uint32_t bh[4][2], bl[4][2];
#pragma unroll
            for (int nt = 0; nt < 4; nt++) {
                const int rb = n0w + nt * 8 + (lane & 7);
                const int cb = ks * 2 + ((lane >> 3) & 1);
                const uint32_t off = sw64(rb, cb);
                LDMX2(bh[nt], bH + off);
                LDMX2(bl[nt], bL + off);
            }
#pragma unroll
            for (int mt = 0; mt < 4; mt++) {
                const int ra = m0w + mt * 16 + (lane & 15);
                const int ca = ks * 2 + (lane >> 4);
                const uint32_t off = sw64(ra, ca);
                uint32_t ah[4], al[4];
                LDMX4(ah, aH + off);
                LDMX4(al, aL + off);
#pragma unroll
                for (int nt = 0; nt < 4; nt++) {
                    mma_f16(acc[mt][nt], ah, bh[nt]);
                    mma_f16(acc[mt][nt], ah, bl[nt]);
                    mma_f16(acc[mt][nt], al, bh[nt]);
                }
            }
        }
        __syncthreads();
    }

    // ---- fused RMS-norm epilogue ----
    float* part = (float*)(dsm + (s0 - smem_gen));
    const int ng = warp >> 1;
#pragma unroll
    for (int mt = 0; mt < 4; mt++) {
#pragma unroll
        for (int r = 0; r < 2; r++) {
            float p = 0.0f;
#pragma unroll
            for (int nt = 0; nt < 4; nt++) {
                const float a0 = acc[mt][nt][2*r], a1 = acc[mt][nt][2*r+1];
                p += a0 * a0 + a1 * a1;
            }
            p += __shfl_xor_sync(0xffffffffu, p, 1);
            p += __shfl_xor_sync(0xffffffffu, p, 2);
            if (t == 0)
                part[ng * 128 + m0w + mt * 16 + g + r * 8] = p;
        }
    }
    __syncthreads();

#pragma unroll
    for (int mt = 0; mt < 4; mt++) {
#pragma unroll
        for (int r = 0; r < 2; r++) {
            const int row = m0w + mt * 16 + g + r * 8;
            const float sum = part[row] + part[128 + row]
                            + part[256 + row] + part[384 + row];
            const float rs = rsqrtf(sum * (1.0f / 128.0f) + 1e-6f);
#pragma unroll
            for (int nt = 0; nt < 4; nt++) {
                const int col = n0w + nt * 8 + 2 * t;
                const float2 sv = *(const float2*)(sc + col);
                const float v0 = acc[mt][nt][2*r]   * rs * sv.x;
                const float v1 = acc[mt][nt][2*r+1] * rs * sv.y;
                __half h0, l0, h1, l1;
                split_h(v0, h0, l0); split_h(v1, h1, l1);
                const size_t idx = obase + (size_t)row * 2048 + col;
                *(uint32_t*)(Oh + idx) = pack2h(h0, h1);
                *(uint32_t*)(Ol + idx) = pack2h(l0, l1);
            }
        }
    }
}

__global__ void __launch_bounds__(256, 2) kg_proj(const float* __restrict__ qs,
                                                  const float* __restrict__ ks)
{
    const int z = blockIdx.z;
    const size_t ao = (size_t)blockIdx.y * 128 * 2048;
    const size_t bo = (size_t)blockIdx.x * 128 * 2048;
    const size_t ob = ao + blockIdx.x * 128;
    if (z == 0)
        gemm_qk_3t(g_xh + ao, g_xl + ao, g_wqh + bo, g_wql + bo,
                   qs, g_qnh, g_qnl, ob, E_);
    else if (z == 1)
        gemm_qk_3t(g_xh + ao, g_xl + ao, g_wkh + bo, g_wkl + bo,
                   ks, g_knh, g_knl, ob, E_);
    else {
        const int b  = blockIdx.y >> 4;
        const int zz = b * 16 + blockIdx.x;          // head = blockIdx.x
        const int s0g = (blockIdx.y & 15) * 128;
        gemm_f16_1t<true>(g_xh + ao, g_wvh + bo, nullptr,
                          g_vth + (size_t)zz * D_ * S_, s0g, E_);
    }
}

__global__ void __launch_bounds__(256, 2) kg_out(float* out)
{
    const size_t ao = (size_t)blockIdx.y * 128 * 2048;
    const size_t bo = (size_t)blockIdx.x * 128 * 2048;
    gemm_f16_1t<false>(g_aoh + ao, g_woh + bo,
                       out + ao + blockIdx.x * 128, nullptr, 0, HD);
}

// ---------------------------------------------------------------------------
// Flash attention. S-path fp16 3-term, PV fp16 2-term, output single fp16.
// SMEM: QH 32K | QL 32K | 2 st x (KH 16K | KL 16K | V 16K) | PH 16K | PL 16K
// ---------------------------------------------------------------------------
#define FL_SMEM 197632

__global__ void __launch_bounds__(256, 1) k_flash()
{
    extern __shared__ char dsm[];
    const uint32_t s0 = ((uint32_t)__cvta_generic_to_shared(dsm) + 1023) & ~1023u;
    const uint32_t PH = s0 + 163840u, PL = s0 + 180224u;

    const int qt = blockIdx.x, z = blockIdx.y, b = z >> 4, h = z & 15;
    const int tid = threadIdx.x, warp = tid >> 5, lane = tid & 31;
    const int g = lane >> 2, t = lane & 3;

    // ---- Q load (once)
    {
        const __half* qsrc[2] = {g_qnh, g_qnl};
#pragma unroll
        for (int sp = 0; sp < 2; sp++) {
            const uint32_t db = s0 + (uint32_t)sp * 32768u;
#pragma unroll
            for (int j = 0; j < 8; j++) {
                const int i = tid + j * 256;
                const int pl = i >> 10, row = (i >> 3) & 127, ch = i & 7;
                cpa16(db + pl * 16384u + sw128(row, ch),
                      qsrc[sp] + ((size_t)(b * S_ + qt * 128 + row)) * 2048
                               + h * 128 + pl * 64 + ch * 8);
            }
        }
    }

    auto issue_kv = [&](int it) {
        const uint32_t stb = s0 + 65536u + (uint32_t)(it & 1) * 49152u;
        const int kt = it * 64;
        const __half* ksrc[2] = {g_knh, g_knl};
#pragma unroll
        for (int sp = 0; sp < 2; sp++) {
            const uint32_t kb = stb + (uint32_t)sp * 16384u;
#pragma unroll
            for (int j = 0; j < 4; j++) {
                const int i = tid + j * 256;
                const int pl = i >> 9, row = (i >> 3) & 63, ch = i & 7;
                cpa16(kb + pl * 8192u + sw128(row, ch),
                      ksrc[sp] + ((size_t)(b * S_ + kt + row)) * 2048
                               + h * 128 + pl * 64 + ch * 8);
            }
        }
#pragma unroll
        for (int j = 0; j < 4; j++) {
            const int i = tid + j * 256;
            const int row = i >> 3, ch = i & 7;
            cpa16(stb + 32768u + sw128(row, ch),
                  g_vth + (size_t)z * D_ * S_ + (size_t)row * S_ + kt + ch * 8);
        }
        CP_COMMIT();
    };

    issue_kv(0);

    float oacc[16][4];
#pragma unroll
    for (int i = 0; i < 16; i++)
#pragma unroll
        for (int e = 0; e < 4; e++) oacc[i][e] = 0.0f;
    float mprev0 = -1e30f, mprev1 = -1e30f, lsum0 = 0.0f, lsum1 = 0.0f;

    for (int it = 0; it < 32; it++) {
        if (it + 1 < 32) { issue_kv(it + 1); cp_wait<1>(); }
        else             { cp_wait<0>(); }
        __syncthreads();

        const uint32_t stb = s0 + 65536u + (uint32_t)(it & 1) * 49152u;

        float sacc[8][4];
#pragma unroll
        for (int i = 0; i < 8; i++)
#pragma unroll
            for (int e = 0; e < 4; e++) sacc[i][e] = 0.0f;

#pragma unroll
        for (int p = 0; p < 2; p++) {
            const uint32_t qh = s0 + p * 16384u;
            const uint32_t ql = s0 + 32768u + p * 16384u;
            const uint32_t kh = stb + p * 8192u;
            const uint32_t kl = stb + 16384u + p * 8192u;
#pragma unroll
            for (int ks = 0; ks < 4; ks++) {
                const int ra = warp * 16 + (lane & 15);
                const int ca = ks * 2 + (lane >> 4);
                const uint32_t offA = sw128(ra, ca);
                uint32_t ah[4], al[4];
                LDMX4(ah, qh + offA);
                LDMX4(al, ql + offA);
#pragma unroll
                for (int np = 0; np < 4; np++) {
                    const int rb = np * 16 + (lane & 15);
                    const int cb = ks * 2 + (lane >> 4);
                    const uint32_t offB = sw128(rb, cb);
                    uint32_t b4h[4], b4l[4];
                    LDMX4(b4h, kh + offB);
                    LDMX4(b4l, kl + offB);
                    uint32_t be[2] = {b4h[0], b4h[2]};
                    uint32_t bo[2] = {b4h[1], b4h[3]};
                    uint32_t le[2] = {b4l[0], b4l[2]};
                    uint32_t lo[2] = {b4l[1], b4l[3]};
                    mma_f16(sacc[2*np],   ah, be);
                    mma_f16(sacc[2*np],   ah, le);
                    mma_f16(sacc[2*np],   al, be);
                    mma_f16(sacc[2*np+1], ah, bo);
                    mma_f16(sacc[2*np+1], ah, lo);
                    mma_f16(sacc[2*np+1], al, bo);
                }
            }
        }

        // ---- online softmax
        float mx0 = -1e30f, mx1 = -1e30f;
#pragma unroll
        for (int i = 0; i < 8; i++) {
            mx0 = fmaxf(mx0, fmaxf(sacc[i][0], sacc[i][1]));
            mx1 = fmaxf(mx1, fmaxf(sacc[i][2], sacc[i][3]));
        }
        mx0 = fmaxf(mx0, __shfl_xor_sync(0xffffffffu, mx0, 1));
        mx0 = fmaxf(mx0, __shfl_xor_sync(0xffffffffu, mx0, 2));
        mx1 = fmaxf(mx1, __shfl_xor_sync(0xffffffffu, mx1, 1));
        mx1 = fmaxf(mx1, __shfl_xor_sync(0xffffffffu, mx1, 2));

        const float mn0 = fmaxf(mprev0, mx0);
        const float mn1 = fmaxf(mprev1, mx1);
        const float sc0 = __expf(mprev0 - mn0);
        const float sc1 = __expf(mprev1 - mn1);
        mprev0 = mn0; mprev1 = mn1;

        float su0 = 0.0f, su1 = 0.0f;
#pragma unroll
        for (int i = 0; i < 8; i++) {
            sacc[i][0] = __expf(sacc[i][0] - mn0);
            sacc[i][1] = __expf(sacc[i][1] - mn0);
            sacc[i][2] = __expf(sacc[i][2] - mn1);
            sacc[i][3] = __expf(sacc[i][3] - mn1);
            su0 += sacc[i][0] + sacc[i][1];
            su1 += sacc[i][2] + sacc[i][3];
        }
        su0 += __shfl_xor_sync(0xffffffffu, su0, 1);
        su0 += __shfl_xor_sync(0xffffffffu, su0, 2);
        su1 += __shfl_xor_sync(0xffffffffu, su1, 1);
        su1 += __shfl_xor_sync(0xffffffffu, su1, 2);
        lsum0 = lsum0 * sc0 + su0;
        lsum1 = lsum1 * sc1 + su1;

#pragma unroll
        for (int i = 0; i < 16; i++) {
            oacc[i][0] *= sc0; oacc[i][1] *= sc0;
            oacc[i][2] *= sc1; oacc[i][3] *= sc1;
        }

        // ---- store P hi/lo to SMEM (A-operand layout)
        const uint32_t smem_gen = (uint32_t)__cvta_generic_to_shared(dsm);
#pragma unroll
        for (int nt = 0; nt < 8; nt++) {
#pragma unroll
            for (int r = 0; r < 2; r++) {
                const float v0 = sacc[nt][2*r], v1 = sacc[nt][2*r+1];
                __half h0, l0, h1, l1;
                split_h(v0, h0, l0); split_h(v1, h1, l1);
                const int row = warp * 16 + g + r * 8;
                const uint32_t off = row * 128u + ((nt ^ (row & 7)) << 4) + t * 4u;
                *(uint32_t*)(dsm + (PH + off - smem_gen)) = pack2h(h0, h1);
                *(uint32_t*)(dsm + (PL + off - smem_gen)) = pack2h(l0, l1);
            }
        }
        __syncwarp();

        // ---- O += (Ph+Pl) V
        const uint32_t vb = stb + 32768u;
#pragma unroll
        for (int ks = 0; ks < 4; ks++) {
            const int ra = warp * 16 + (lane & 15);
            const int ca = ks * 2 + (lane >> 4);
            const uint32_t offA = sw128(ra, ca);
            uint32_t ph_[4], pl_[4];
            LDMX4(ph_, PH + offA);
            LDMX4(pl_, PL + offA);
#pragma unroll
            for (int np = 0; np < 8; np++) {
                const int rb = np * 16 + (lane & 15);
                const int cb = ks * 2 + (lane >> 4);
                const uint32_t offB = sw128(rb, cb);
                uint32_t v4[4];
                LDMX4(v4, vb + offB);
                uint32_t be[2] = {v4[0], v4[2]};
                uint32_t bo[2] = {v4[1], v4[3]};
                mma_f16(oacc[2*np],   ph_, be);
                mma_f16(oacc[2*np],   pl_, be);
                mma_f16(oacc[2*np+1], ph_, bo);
                mma_f16(oacc[2*np+1], pl_, bo);
            }
        }
        __syncthreads();
    }

    // ---- epilogue: O / l -> single fp16
    const float inv0 = 1.0f / lsum0, inv1 = 1.0f / lsum1;
    const int row0 = b * S_ + qt * 128 + warp * 16 + g;
#pragma unroll
    for (int nt = 0; nt < 16; nt++) {
        const int col = h * 128 + nt * 8 + 2 * t;
        *(uint32_t*)(g_aoh + (size_t)row0 * 2048 + col) =
            pack2h(__float2half_rn(oacc[nt][0] * inv0),
                   __float2half_rn(oacc[nt][1] * inv0));
        *(uint32_t*)(g_aoh + (size_t)(row0 + 8) * 2048 + col) =
            pack2h(__float2half_rn(oacc[nt][2] * inv1),
                   __float2half_rn(oacc[nt][3] * inv1));
    }
}

// ---------------------------------------------------------------------------
// Prep kernels
// ---------------------------------------------------------------------------
__global__ void k_prep_w(const float* __restrict__ wq, const float* __restrict__ wk,
                         const float* __restrict__ wv, const float* __restrict__ wo)
{
    __shared__ float tbuf[32][33];
    const int z = blockIdx.z;
    const float* src = (z == 0) ? wq : (z == 1) ? wk : (z == 2) ? wv : wo;
    __half* dh = (z == 0) ? g_wqh : (z == 1) ? g_wkh : (z == 2) ? g_wvh : g_woh;
    __half* dl = (z == 0) ? g_wql : (z == 1) ? g_wkl : nullptr;
    const int x0 = blockIdx.x * 32, y0 = blockIdx.y * 32;
    const int tx = threadIdx.x, ty = threadIdx.y;
#pragma unroll
    for (int j = ty; j < 32; j += 8)
        tbuf[j][tx] = src[(size_t)(y0 + j) * 2048 + x0 + tx];
    __syncthreads();
#pragma unroll
    for (int j = ty; j < 32; j += 8) {
        const float v = tbuf[tx][j];
        const size_t idx = (size_t)(x0 + j) * 2048 + y0 + tx;
        if (dl) {
            __half h, l; split_h(v, h, l);
            dh[idx] = h; dl[idx] = l;
        } else {
            dh[idx] = __float2half_rn(v);
        }
    }
}

__global__ void k_prep_x(const float* __restrict__ x)
{
    const size_t i = ((size_t)blockIdx.x * 256 + threadIdx.x) * 4;
    const float4 v = *(const float4*)(x + i);
    __half h[4], l[4];
    split_h(v.x, h[0], l[0]); split_h(v.y, h[1], l[1]);
    split_h(v.z, h[2], l[2]); split_h(v.w, h[3], l[3]);
    *(uint2*)(g_xh + i) = *(uint2*)h;
    *(uint2*)(g_xl + i) = *(uint2*)l;
}

// ---------------------------------------------------------------------------
extern "C" void kernel_launch(void* const* d_in, const int* in_sizes, int n_in,
                              void* d_out, int out_size)
{
    const float* x  = (const float*)d_in[0];
    const float* wq = (const float*)d_in[1];
    const float* wk = (const float*)d_in[2];
    const float* wv = (const float*)d_in[3];
    const float* wo = (const float*)d_in[4];
    const float* qs = (const float*)d_in[5];
    const float* ks = (const float*)d_in[6];
    float* out = (float*)d_out;

    constexpr int SMEMG = 2 * 32768 + 1024;  // 66560 -> 2 CTAs/SM
    cudaFuncSetAttribute(kg_proj, cudaFuncAttributeMaxDynamicSharedMemorySize, SMEMG);
    cudaFuncSetAttribute(kg_out,  cudaFuncAttributeMaxDynamicSharedMemorySize, SMEMG);
    cudaFuncSetAttribute(k_flash, cudaFuncAttributeMaxDynamicSharedMemorySize, FL_SMEM);

    k_prep_w <<<dim3(64, 64, 4), dim3(32, 8)>>>(wq, wk, wv, wo);
    k_prep_x <<<8192, 256>>>(x);
    kg_proj  <<<dim3(16, 32, 3), 256, SMEMG>>>(qs, ks);
    k_flash  <<<dim3(16, 32), 256, FL_SMEM>>>();
    kg_out   <<<dim3(16, 32), 256, SMEMG>>>(out);
}